// round 1
// baseline (speedup 1.0000x reference)
#include <cuda_runtime.h>
#include <math.h>

// ---------------- constants ----------------
#define Bc   8
#define Sc   256
#define Dc   512
#define Hc   8
#define DKc  256
#define HDc  2048   // H*DK
#define DFFc 2048
#define Lc   4

#define BSD  (Bc*Sc*Dc)      // 1,048,576
#define BSHD (Bc*Sc*HDc)     // 4,194,304
#define BHSS (Bc*Hc*Sc*Sc)   // 4,194,304
#define BSF  (Bc*Sc*DFFc)    // 4,194,304

// ---------------- scratch (static device globals; no allocations) ----------------
__device__ __align__(16) float g_x [BSD];
__device__ __align__(16) float g_x2[BSD];
__device__ __align__(16) float g_q [BSHD];
__device__ __align__(16) float g_k [BSHD];
__device__ __align__(16) float g_v [BSHD];
__device__ __align__(16) float g_s [BHSS];
__device__ __align__(16) float g_o [BSHD];
__device__ __align__(16) float g_f [BSF];

// ---------------- embed: x = data*sqrt(D) + pe + seg_emb[view_idx*S] ----------------
__global__ void embed_kernel(const float* __restrict__ data,
                             const float* __restrict__ seg,
                             const int*   __restrict__ view_idx,
                             float* __restrict__ x)
{
    int idx = blockIdx.x * blockDim.x + threadIdx.x;
    if (idx >= BSD) return;
    int d = idx & (Dc - 1);
    int s = (idx / Dc) & (Sc - 1);
    // pe[s,c] = (c even? sin : cos)( s * 256^(-2c/D) ) ; 256^(2c/512) = 2^(c/32)
    float angle = (float)s * exp2f(-(float)d * (1.0f / 32.0f));
    float pe = (d & 1) ? (float)cos((double)angle) : (float)sin((double)angle);
    int seg_row = view_idx[0] * Sc;  // 0 in practice
    x[idx] = data[idx] * 22.62741699796952f + pe + seg[seg_row * Dc + d];
}

// ---------------- layernorm (ddof=1 variance, denom = sqrt(var)+eps) ----------------
// one block per row of 512; 128 threads, float4 each
__global__ void layernorm_kernel(const float* __restrict__ x, float* __restrict__ y,
                                 const float* __restrict__ alpha,
                                 const float* __restrict__ beta)
{
    int row = blockIdx.x;
    int t = threadIdx.x;              // 0..127
    const float4* xr = (const float4*)(x + (size_t)row * Dc);
    float4 v = xr[t];

    __shared__ float sh[4];
    float s = v.x + v.y + v.z + v.w;
    #pragma unroll
    for (int o = 16; o; o >>= 1) s += __shfl_xor_sync(0xFFFFFFFFu, s, o);
    if ((t & 31) == 0) sh[t >> 5] = s;
    __syncthreads();
    float tot = sh[0] + sh[1] + sh[2] + sh[3];
    float mean = tot * (1.0f / (float)Dc);

    float dx = v.x - mean, dy = v.y - mean, dz = v.z - mean, dw = v.w - mean;
    float q = dx*dx + dy*dy + dz*dz + dw*dw;
    __syncthreads();
    #pragma unroll
    for (int o = 16; o; o >>= 1) q += __shfl_xor_sync(0xFFFFFFFFu, q, o);
    if ((t & 31) == 0) sh[t >> 5] = q;
    __syncthreads();
    float var = (sh[0] + sh[1] + sh[2] + sh[3]) * (1.0f / (float)(Dc - 1));
    float inv = 1.0f / (sqrtf(var) + 1e-6f);

    float4 a = ((const float4*)alpha)[t];
    float4 b = ((const float4*)beta)[t];
    float4 o;
    o.x = a.x * dx * inv + b.x;
    o.y = a.y * dy * inv + b.y;
    o.z = a.z * dz * inv + b.z;
    o.w = a.w * dw * inv + b.w;
    ((float4*)(y + (size_t)row * Dc))[t] = o;
}

// ---------------- softmax over rows of 256 (one warp per row) ----------------
__global__ void softmax_kernel(float* __restrict__ s)
{
    int gw = (blockIdx.x * blockDim.x + threadIdx.x) >> 5;
    if (gw >= Bc * Hc * Sc) return;
    int lane = threadIdx.x & 31;
    float* r = s + (size_t)gw * Sc + lane * 8;
    float4 a = *(float4*)r;
    float4 b = *(float4*)(r + 4);
    float m = fmaxf(fmaxf(fmaxf(a.x, a.y), fmaxf(a.z, a.w)),
                    fmaxf(fmaxf(b.x, b.y), fmaxf(b.z, b.w)));
    #pragma unroll
    for (int o = 16; o; o >>= 1) m = fmaxf(m, __shfl_xor_sync(0xFFFFFFFFu, m, o));
    a.x = expf(a.x - m); a.y = expf(a.y - m); a.z = expf(a.z - m); a.w = expf(a.w - m);
    b.x = expf(b.x - m); b.y = expf(b.y - m); b.z = expf(b.z - m); b.w = expf(b.w - m);
    float sum = a.x + a.y + a.z + a.w + b.x + b.y + b.z + b.w;
    #pragma unroll
    for (int o = 16; o; o >>= 1) sum += __shfl_xor_sync(0xFFFFFFFFu, sum, o);
    float inv = 1.0f / sum;
    a.x *= inv; a.y *= inv; a.z *= inv; a.w *= inv;
    b.x *= inv; b.y *= inv; b.z *= inv; b.w *= inv;
    *(float4*)r = a;
    *(float4*)(r + 4) = b;
}

// ---------------- SGEMM 128x128x8, 8x8 per thread, batched + fused epilogue ----------
// C = epilogue( A @ B (+bias) ) ; TRANSB: B is [N,K] row-major (C = A @ B^T)
// batching: z -> (zb = z/zdiv, zi = z%zdiv); ptr += zb*s0 + zi*s1
template<bool TRANSB>
__global__ __launch_bounds__(256)
void sgemm_kernel(const float* __restrict__ A, int lda, long long sA0, long long sA1,
                  const float* __restrict__ Bp, int ldb, long long sB0, long long sB1,
                  float* __restrict__ C, int ldc, long long sC0, long long sC1,
                  int zdiv, int K,
                  const float* __restrict__ bias,
                  const float* __restrict__ residual,
                  int relu, float scale,
                  const int* __restrict__ mask)
{
    int z = blockIdx.z;
    int zb = z / zdiv, zi = z - zb * zdiv;
    A  += zb * sA0 + zi * sA1;
    Bp += zb * sB0 + zi * sB1;
    C  += zb * sC0 + zi * sC1;
    const float* res = residual ? residual + zb * sC0 + zi * sC1 : nullptr;

    __shared__ float As[8][128];
    __shared__ float Bs[8][128];

    int tid = threadIdx.x;
    int ty = tid >> 4, tx = tid & 15;
    int rowBase = blockIdx.y * 128 + ty * 8;
    int colBase = blockIdx.x * 128 + tx * 8;

    int ar = tid >> 1, ac = (tid & 1) * 4;  // A tile: 128 rows x 8 k
    const float* Aload = A + (size_t)(blockIdx.y * 128 + ar) * lda + ac;

    float acc[8][8];
    #pragma unroll
    for (int i = 0; i < 8; i++)
        #pragma unroll
        for (int j = 0; j < 8; j++) acc[i][j] = 0.0f;

    for (int k0 = 0; k0 < K; k0 += 8) {
        float4 av = *(const float4*)(Aload + k0);
        As[ac + 0][ar] = av.x; As[ac + 1][ar] = av.y;
        As[ac + 2][ar] = av.z; As[ac + 3][ar] = av.w;
        if (TRANSB) {
            int bn = tid >> 1, bk = (tid & 1) * 4;
            float4 bv = *(const float4*)(Bp + (size_t)(blockIdx.x * 128 + bn) * ldb + k0 + bk);
            Bs[bk + 0][bn] = bv.x; Bs[bk + 1][bn] = bv.y;
            Bs[bk + 2][bn] = bv.z; Bs[bk + 3][bn] = bv.w;
        } else {
            int bk = tid >> 5, bn = (tid & 31) * 4;
            float4 bv = *(const float4*)(Bp + (size_t)(k0 + bk) * ldb + blockIdx.x * 128 + bn);
            *(float4*)&Bs[bk][bn] = bv;
        }
        __syncthreads();
        #pragma unroll
        for (int kk = 0; kk < 8; kk++) {
            float4 a0 = *(const float4*)&As[kk][ty * 8];
            float4 a1 = *(const float4*)&As[kk][ty * 8 + 4];
            float4 b0 = *(const float4*)&Bs[kk][tx * 8];
            float4 b1 = *(const float4*)&Bs[kk][tx * 8 + 4];
            float aa[8] = {a0.x, a0.y, a0.z, a0.w, a1.x, a1.y, a1.z, a1.w};
            float bb[8] = {b0.x, b0.y, b0.z, b0.w, b1.x, b1.y, b1.z, b1.w};
            #pragma unroll
            for (int i = 0; i < 8; i++)
                #pragma unroll
                for (int j = 0; j < 8; j++)
                    acc[i][j] = fmaf(aa[i], bb[j], acc[i][j]);
        }
        __syncthreads();
    }

    // epilogue
    float bcol[8];
    int mk[8];
    #pragma unroll
    for (int j = 0; j < 8; j++) {
        bcol[j] = bias ? bias[colBase + j] : 0.0f;
        mk[j]   = mask ? mask[zb * Sc + colBase + j] : 0;
    }
    #pragma unroll
    for (int i = 0; i < 8; i++) {
        size_t roff = (size_t)(rowBase + i) * ldc + colBase;
        float out[8];
        #pragma unroll
        for (int j = 0; j < 8; j++) {
            float c = acc[i][j] + bcol[j];
            c *= scale;
            if (mask && mk[j]) c = -1e9f;
            if (relu) c = fmaxf(c, 0.0f);
            if (res) c += res[roff + j];
            out[j] = c;
        }
        *(float4*)&C[roff]     = make_float4(out[0], out[1], out[2], out[3]);
        *(float4*)&C[roff + 4] = make_float4(out[4], out[5], out[6], out[7]);
    }
}

// ---------------- host-side helpers ----------------
static void sgemm(const float* A, int lda, long long sA0, long long sA1,
                  const float* B, int ldb, long long sB0, long long sB1,
                  float* C, int ldc, long long sC0, long long sC1,
                  int zdiv, int M, int N, int K, int nz,
                  const float* bias, const float* res, int relu, float scale,
                  const int* mask, bool transb)
{
    dim3 grid(N / 128, M / 128, nz), block(256);
    if (transb)
        sgemm_kernel<true><<<grid, block>>>(A, lda, sA0, sA1, B, ldb, sB0, sB1,
                                            C, ldc, sC0, sC1, zdiv, K,
                                            bias, res, relu, scale, mask);
    else
        sgemm_kernel<false><<<grid, block>>>(A, lda, sA0, sA1, B, ldb, sB0, sB1,
                                             C, ldc, sC0, sC1, zdiv, K,
                                             bias, res, relu, scale, mask);
}

extern "C" void kernel_launch(void* const* d_in, const int* in_sizes, int n_in,
                              void* d_out, int out_size)
{
    const float* data    = (const float*)d_in[0];
    const int*   attn_m  = (const int*)  d_in[1];
    const int*   view_ix = (const int*)  d_in[2];
    const float* seg     = (const float*)d_in[3];
    const float* Wq = (const float*)d_in[4];
    const float* bq = (const float*)d_in[5];
    const float* Wk = (const float*)d_in[6];
    const float* bk = (const float*)d_in[7];
    const float* Wv = (const float*)d_in[8];
    const float* bv = (const float*)d_in[9];
    const float* Wo = (const float*)d_in[10];
    const float* bo = (const float*)d_in[11];
    const float* W1 = (const float*)d_in[12];
    const float* b1 = (const float*)d_in[13];
    const float* W2 = (const float*)d_in[14];
    const float* b2 = (const float*)d_in[15];
    const float* alpha1 = (const float*)d_in[16];
    const float* bias1  = (const float*)d_in[17];
    const float* alpha2 = (const float*)d_in[18];
    const float* bias2  = (const float*)d_in[19];
    const float* alphaf = (const float*)d_in[20];
    const float* biasf  = (const float*)d_in[21];
    float* out = (float*)d_out;

    static float *px = nullptr, *px2, *pq, *pk, *pv, *ps, *po, *pf;
    if (!px) {
        cudaGetSymbolAddress((void**)&px,  g_x);
        cudaGetSymbolAddress((void**)&px2, g_x2);
        cudaGetSymbolAddress((void**)&pq,  g_q);
        cudaGetSymbolAddress((void**)&pk,  g_k);
        cudaGetSymbolAddress((void**)&pv,  g_v);
        cudaGetSymbolAddress((void**)&ps,  g_s);
        cudaGetSymbolAddress((void**)&po,  g_o);
        cudaGetSymbolAddress((void**)&pf,  g_f);
    }

    const float iscale = 0.0625f; // 1/sqrt(256)

    embed_kernel<<<(BSD + 255) / 256, 256>>>(data, seg, view_ix, px);

    for (int i = 0; i < Lc; i++) {
        layernorm_kernel<<<Bc * Sc, 128>>>(px, px2, alpha1 + i * Dc, bias1 + i * Dc);

        // Q, K, V projections: [2048,512] @ [512,2048]
        sgemm(px2, Dc, 0, 0, Wq + (long long)i * Dc * HDc, HDc, 0, 0,
              pq, HDc, 0, 0, 1, Bc * Sc, HDc, Dc, 1,
              bq + i * HDc, nullptr, 0, 1.0f, nullptr, false);
        sgemm(px2, Dc, 0, 0, Wk + (long long)i * Dc * HDc, HDc, 0, 0,
              pk, HDc, 0, 0, 1, Bc * Sc, HDc, Dc, 1,
              bk + i * HDc, nullptr, 0, 1.0f, nullptr, false);
        sgemm(px2, Dc, 0, 0, Wv + (long long)i * Dc * HDc, HDc, 0, 0,
              pv, HDc, 0, 0, 1, Bc * Sc, HDc, Dc, 1,
              bv + i * HDc, nullptr, 0, 1.0f, nullptr, false);

        // scores[b,h] = Q_bh @ K_bh^T * 1/16, masked ; per-(b,h) batched NT
        sgemm(pq, HDc, (long long)Sc * HDc, DKc,
              pk, HDc, (long long)Sc * HDc, DKc,
              ps, Sc, (long long)Hc * Sc * Sc, (long long)Sc * Sc,
              Hc, Sc, Sc, DKc, Bc * Hc,
              nullptr, nullptr, 0, iscale, attn_m, true);

        softmax_kernel<<<(Bc * Hc * Sc) / 8, 256>>>(ps);

        // o[b,h] = P_bh @ V_bh   -> written into [B,S,H,DK] concat layout
        sgemm(ps, Sc, (long long)Hc * Sc * Sc, (long long)Sc * Sc,
              pv, HDc, (long long)Sc * HDc, DKc,
              po, HDc, (long long)Sc * HDc, DKc,
              Hc, Sc, DKc, Sc, Bc * Hc,
              nullptr, nullptr, 0, 1.0f, nullptr, false);

        // x = x + (o @ Wo + bo)
        sgemm(po, HDc, 0, 0, Wo + (long long)i * HDc * Dc, Dc, 0, 0,
              px, Dc, 0, 0, 1, Bc * Sc, Dc, HDc, 1,
              bo + i * Dc, px, 0, 1.0f, nullptr, false);

        layernorm_kernel<<<Bc * Sc, 128>>>(px, px2, alpha2 + i * Dc, bias2 + i * Dc);

        // ff = relu(x2 @ W1 + b1)
        sgemm(px2, Dc, 0, 0, W1 + (long long)i * Dc * DFFc, DFFc, 0, 0,
              pf, DFFc, 0, 0, 1, Bc * Sc, DFFc, Dc, 1,
              b1 + i * DFFc, nullptr, 1, 1.0f, nullptr, false);

        // x = x + (ff @ W2 + b2)
        sgemm(pf, DFFc, 0, 0, W2 + (long long)i * DFFc * Dc, Dc, 0, 0,
              px, Dc, 0, 0, 1, Bc * Sc, Dc, DFFc, 1,
              b2 + i * Dc, px, 0, 1.0f, nullptr, false);
    }

    layernorm_kernel<<<Bc * Sc, 128>>>(px, out, alphaf, biasf);
}

// round 2
// speedup vs baseline: 2.3612x; 2.3612x over previous
#include <cuda_runtime.h>
#include <math.h>
#include <stdint.h>

// ---------------- constants ----------------
#define Bc   8
#define Sc   256
#define Dc   512
#define Hc   8
#define DKc  256
#define HDc  2048
#define DFFc 2048
#define Lc   4

#define BSD  (Bc*Sc*Dc)
#define BSHD (Bc*Sc*HDc)
#define BHSS (Bc*Hc*Sc*Sc)
#define BSF  (Bc*Sc*DFFc)

// ---------------- scratch ----------------
__device__ __align__(16) float g_x [BSD];
__device__ __align__(16) float g_x2[BSD];
__device__ __align__(16) float g_q [BSHD];
__device__ __align__(16) float g_k [BSHD];
__device__ __align__(16) float g_v [BSHD];
__device__ __align__(16) float g_s [BHSS];
__device__ __align__(16) float g_o [BSHD];
__device__ __align__(16) float g_f [BSF];

// ---------------- embed ----------------
__global__ void embed_kernel(const float* __restrict__ data,
                             const float* __restrict__ seg,
                             const int*   __restrict__ view_idx,
                             float* __restrict__ x)
{
    int idx = blockIdx.x * blockDim.x + threadIdx.x;
    if (idx >= BSD) return;
    int d = idx & (Dc - 1);
    int s = (idx / Dc) & (Sc - 1);
    float angle = (float)s * exp2f(-(float)d * (1.0f / 32.0f));
    float pe = (d & 1) ? (float)cos((double)angle) : (float)sin((double)angle);
    int seg_row = view_idx[0] * Sc;
    x[idx] = data[idx] * 22.62741699796952f + pe + seg[seg_row * Dc + d];
}

// ---------------- layernorm (ddof=1, denom = sqrt(var)+eps) ----------------
__global__ void layernorm_kernel(const float* __restrict__ x, float* __restrict__ y,
                                 const float* __restrict__ alpha,
                                 const float* __restrict__ beta)
{
    int row = blockIdx.x;
    int t = threadIdx.x;
    const float4* xr = (const float4*)(x + (size_t)row * Dc);
    float4 v = xr[t];

    __shared__ float sh[4];
    float s = v.x + v.y + v.z + v.w;
    #pragma unroll
    for (int o = 16; o; o >>= 1) s += __shfl_xor_sync(0xFFFFFFFFu, s, o);
    if ((t & 31) == 0) sh[t >> 5] = s;
    __syncthreads();
    float mean = (sh[0] + sh[1] + sh[2] + sh[3]) * (1.0f / (float)Dc);

    float dx = v.x - mean, dy = v.y - mean, dz = v.z - mean, dw = v.w - mean;
    float q = dx*dx + dy*dy + dz*dz + dw*dw;
    __syncthreads();
    #pragma unroll
    for (int o = 16; o; o >>= 1) q += __shfl_xor_sync(0xFFFFFFFFu, q, o);
    if ((t & 31) == 0) sh[t >> 5] = q;
    __syncthreads();
    float var = (sh[0] + sh[1] + sh[2] + sh[3]) * (1.0f / (float)(Dc - 1));
    float inv = 1.0f / (sqrtf(var) + 1e-6f);

    float4 a = ((const float4*)alpha)[t];
    float4 b = ((const float4*)beta)[t];
    float4 o;
    o.x = a.x * dx * inv + b.x;
    o.y = a.y * dy * inv + b.y;
    o.z = a.z * dz * inv + b.z;
    o.w = a.w * dw * inv + b.w;
    ((float4*)(y + (size_t)row * Dc))[t] = o;
}

// ---------------- softmax ----------------
__global__ void softmax_kernel(float* __restrict__ s)
{
    int gw = (blockIdx.x * blockDim.x + threadIdx.x) >> 5;
    if (gw >= Bc * Hc * Sc) return;
    int lane = threadIdx.x & 31;
    float* r = s + (size_t)gw * Sc + lane * 8;
    float4 a = *(float4*)r;
    float4 b = *(float4*)(r + 4);
    float m = fmaxf(fmaxf(fmaxf(a.x, a.y), fmaxf(a.z, a.w)),
                    fmaxf(fmaxf(b.x, b.y), fmaxf(b.z, b.w)));
    #pragma unroll
    for (int o = 16; o; o >>= 1) m = fmaxf(m, __shfl_xor_sync(0xFFFFFFFFu, m, o));
    a.x = expf(a.x - m); a.y = expf(a.y - m); a.z = expf(a.z - m); a.w = expf(a.w - m);
    b.x = expf(b.x - m); b.y = expf(b.y - m); b.z = expf(b.z - m); b.w = expf(b.w - m);
    float sum = a.x + a.y + a.z + a.w + b.x + b.y + b.z + b.w;
    #pragma unroll
    for (int o = 16; o; o >>= 1) sum += __shfl_xor_sync(0xFFFFFFFFu, sum, o);
    float inv = 1.0f / sum;
    a.x *= inv; a.y *= inv; a.z *= inv; a.w *= inv;
    b.x *= inv; b.y *= inv; b.z *= inv; b.w *= inv;
    *(float4*)r = a;
    *(float4*)(r + 4) = b;
}

// ---------------- TF32 mma GEMM: 128x128 tile, BK=16, 8 warps (64x32 each) ----------
__device__ __forceinline__ uint32_t f2tf(float f) {
    uint32_t r;
    asm("cvt.rna.tf32.f32 %0, %1;" : "=r"(r) : "f"(f));
    return r;
}

#define SPAD 132  // padded row length (floats); 132%32=4 -> conflict-free frags

template<bool TRANSB>
__global__ __launch_bounds__(256)
void tgemm_kernel(const float* __restrict__ A, int lda, long long sA0, long long sA1,
                  const float* __restrict__ Bp, int ldb, long long sB0, long long sB1,
                  float* __restrict__ C, int ldc, long long sC0, long long sC1,
                  int zdiv, int K,
                  const float* __restrict__ bias,
                  const float* __restrict__ residual,
                  int relu, float scale,
                  const int* __restrict__ mask)
{
    int z = blockIdx.z;
    int zb = z / zdiv, zi = z - zb * zdiv;
    A  += zb * sA0 + zi * sA1;
    Bp += zb * sB0 + zi * sB1;
    C  += zb * sC0 + zi * sC1;
    const float* res = residual ? residual + zb * sC0 + zi * sC1 : nullptr;

    __shared__ uint32_t As[16 * SPAD];
    __shared__ uint32_t Bs[16 * SPAD];

    int t = threadIdx.x;
    int lane = t & 31, warp = t >> 5;
    int wr = warp >> 2;        // 0..1  (m)
    int wc = warp & 3;         // 0..3  (n)
    int lr = lane >> 2;        // 0..7
    int lc = lane & 3;         // 0..3
    int mBase = wr * 64;
    int nBase = wc * 32;

    float acc[4][4][4];
    #pragma unroll
    for (int i = 0; i < 4; i++)
        #pragma unroll
        for (int j = 0; j < 4; j++)
            #pragma unroll
            for (int k = 0; k < 4; k++) acc[i][j][k] = 0.0f;

    // global-load indexing
    int am = t >> 2, ak = (t & 3) * 4;                 // A: two rows am, am+64
    const float* Abase = A + (size_t)(blockIdx.y * 128) * lda;

    for (int k0 = 0; k0 < K; k0 += 16) {
        // --- load A tile (transpose to k-major) ---
        {
            float4 v0 = *(const float4*)(Abase + (size_t)am * lda + k0 + ak);
            float4 v1 = *(const float4*)(Abase + (size_t)(am + 64) * lda + k0 + ak);
            As[(ak + 0) * SPAD + am] = f2tf(v0.x);
            As[(ak + 1) * SPAD + am] = f2tf(v0.y);
            As[(ak + 2) * SPAD + am] = f2tf(v0.z);
            As[(ak + 3) * SPAD + am] = f2tf(v0.w);
            As[(ak + 0) * SPAD + am + 64] = f2tf(v1.x);
            As[(ak + 1) * SPAD + am + 64] = f2tf(v1.y);
            As[(ak + 2) * SPAD + am + 64] = f2tf(v1.z);
            As[(ak + 3) * SPAD + am + 64] = f2tf(v1.w);
        }
        // --- load B tile (to k-major [k][n]) ---
        if (TRANSB) {
            int bn = t >> 2, bkq = (t & 3) * 4;
            float4 v0 = *(const float4*)(Bp + (size_t)(blockIdx.x * 128 + bn) * ldb + k0 + bkq);
            float4 v1 = *(const float4*)(Bp + (size_t)(blockIdx.x * 128 + bn + 64) * ldb + k0 + bkq);
            Bs[(bkq + 0) * SPAD + bn] = f2tf(v0.x);
            Bs[(bkq + 1) * SPAD + bn] = f2tf(v0.y);
            Bs[(bkq + 2) * SPAD + bn] = f2tf(v0.z);
            Bs[(bkq + 3) * SPAD + bn] = f2tf(v0.w);
            Bs[(bkq + 0) * SPAD + bn + 64] = f2tf(v1.x);
            Bs[(bkq + 1) * SPAD + bn + 64] = f2tf(v1.y);
            Bs[(bkq + 2) * SPAD + bn + 64] = f2tf(v1.z);
            Bs[(bkq + 3) * SPAD + bn + 64] = f2tf(v1.w);
        } else {
            int bk = t >> 5, bn = (t & 31) * 4;
            #pragma unroll
            for (int p = 0; p < 2; p++) {
                float4 v = *(const float4*)(Bp + (size_t)(k0 + bk + p * 8) * ldb + blockIdx.x * 128 + bn);
                uint32_t* dst = &Bs[(bk + p * 8) * SPAD + bn];
                dst[0] = f2tf(v.x); dst[1] = f2tf(v.y);
                dst[2] = f2tf(v.z); dst[3] = f2tf(v.w);
            }
        }
        __syncthreads();

        // --- compute: 2 k-steps of 8 ---
        #pragma unroll
        for (int kk = 0; kk < 16; kk += 8) {
            uint32_t af[4][4], bf[4][2];
            #pragma unroll
            for (int mt = 0; mt < 4; mt++) {
                int m = mBase + mt * 16 + lr;
                af[mt][0] = As[(kk + lc) * SPAD + m];
                af[mt][1] = As[(kk + lc) * SPAD + m + 8];
                af[mt][2] = As[(kk + 4 + lc) * SPAD + m];
                af[mt][3] = As[(kk + 4 + lc) * SPAD + m + 8];
            }
            #pragma unroll
            for (int nt = 0; nt < 4; nt++) {
                int n = nBase + nt * 8 + lr;
                bf[nt][0] = Bs[(kk + lc) * SPAD + n];
                bf[nt][1] = Bs[(kk + 4 + lc) * SPAD + n];
            }
            #pragma unroll
            for (int mt = 0; mt < 4; mt++)
                #pragma unroll
                for (int nt = 0; nt < 4; nt++) {
                    asm volatile(
                        "mma.sync.aligned.m16n8k8.row.col.f32.tf32.tf32.f32 "
                        "{%0,%1,%2,%3}, {%4,%5,%6,%7}, {%8,%9}, {%0,%1,%2,%3};"
                        : "+f"(acc[mt][nt][0]), "+f"(acc[mt][nt][1]),
                          "+f"(acc[mt][nt][2]), "+f"(acc[mt][nt][3])
                        : "r"(af[mt][0]), "r"(af[mt][1]), "r"(af[mt][2]), "r"(af[mt][3]),
                          "r"(bf[nt][0]), "r"(bf[nt][1]));
                }
        }
        __syncthreads();
    }

    // ---------------- epilogue ----------------
    #pragma unroll
    for (int mt = 0; mt < 4; mt++) {
        #pragma unroll
        for (int nt = 0; nt < 4; nt++) {
            int row0 = blockIdx.y * 128 + mBase + mt * 16 + lr;
            int col  = blockIdx.x * 128 + nBase + nt * 8 + lc * 2;
            float b0 = bias ? bias[col]     : 0.0f;
            float b1 = bias ? bias[col + 1] : 0.0f;
            int m0 = mask ? mask[zb * Sc + col]     : 0;
            int m1 = mask ? mask[zb * Sc + col + 1] : 0;
            #pragma unroll
            for (int h = 0; h < 2; h++) {
                int row = row0 + h * 8;
                float c0 = acc[mt][nt][h * 2 + 0] + b0;
                float c1 = acc[mt][nt][h * 2 + 1] + b1;
                c0 *= scale; c1 *= scale;
                if (mask) { if (m0) c0 = -1e9f; if (m1) c1 = -1e9f; }
                if (relu) { c0 = fmaxf(c0, 0.0f); c1 = fmaxf(c1, 0.0f); }
                size_t off = (size_t)row * ldc + col;
                if (res) {
                    float2 r2 = *(const float2*)(res + off);
                    c0 += r2.x; c1 += r2.y;
                }
                *(float2*)(C + off) = make_float2(c0, c1);
            }
        }
    }
}

// ---------------- host-side helper ----------------
static void tgemm(const float* A, int lda, long long sA0, long long sA1,
                  const float* B, int ldb, long long sB0, long long sB1,
                  float* C, int ldc, long long sC0, long long sC1,
                  int zdiv, int M, int N, int K, int nz,
                  const float* bias, const float* res, int relu, float scale,
                  const int* mask, bool transb)
{
    dim3 grid(N / 128, M / 128, nz), block(256);
    if (transb)
        tgemm_kernel<true><<<grid, block>>>(A, lda, sA0, sA1, B, ldb, sB0, sB1,
                                            C, ldc, sC0, sC1, zdiv, K,
                                            bias, res, relu, scale, mask);
    else
        tgemm_kernel<false><<<grid, block>>>(A, lda, sA0, sA1, B, ldb, sB0, sB1,
                                             C, ldc, sC0, sC1, zdiv, K,
                                             bias, res, relu, scale, mask);
}

extern "C" void kernel_launch(void* const* d_in, const int* in_sizes, int n_in,
                              void* d_out, int out_size)
{
    const float* data    = (const float*)d_in[0];
    const int*   attn_m  = (const int*)  d_in[1];
    const int*   view_ix = (const int*)  d_in[2];
    const float* seg     = (const float*)d_in[3];
    const float* Wq = (const float*)d_in[4];
    const float* bq = (const float*)d_in[5];
    const float* Wk = (const float*)d_in[6];
    const float* bk = (const float*)d_in[7];
    const float* Wv = (const float*)d_in[8];
    const float* bv = (const float*)d_in[9];
    const float* Wo = (const float*)d_in[10];
    const float* bo = (const float*)d_in[11];
    const float* W1 = (const float*)d_in[12];
    const float* b1 = (const float*)d_in[13];
    const float* W2 = (const float*)d_in[14];
    const float* b2 = (const float*)d_in[15];
    const float* alpha1 = (const float*)d_in[16];
    const float* bias1  = (const float*)d_in[17];
    const float* alpha2 = (const float*)d_in[18];
    const float* bias2  = (const float*)d_in[19];
    const float* alphaf = (const float*)d_in[20];
    const float* biasf  = (const float*)d_in[21];
    float* out = (float*)d_out;

    static float *px = nullptr, *px2, *pq, *pk, *pv, *ps, *po, *pf;
    if (!px) {
        cudaGetSymbolAddress((void**)&px,  g_x);
        cudaGetSymbolAddress((void**)&px2, g_x2);
        cudaGetSymbolAddress((void**)&pq,  g_q);
        cudaGetSymbolAddress((void**)&pk,  g_k);
        cudaGetSymbolAddress((void**)&pv,  g_v);
        cudaGetSymbolAddress((void**)&ps,  g_s);
        cudaGetSymbolAddress((void**)&po,  g_o);
        cudaGetSymbolAddress((void**)&pf,  g_f);
    }

    const float iscale = 0.0625f;

    embed_kernel<<<(BSD + 255) / 256, 256>>>(data, seg, view_ix, px);

    for (int i = 0; i < Lc; i++) {
        layernorm_kernel<<<Bc * Sc, 128>>>(px, px2, alpha1 + i * Dc, bias1 + i * Dc);

        tgemm(px2, Dc, 0, 0, Wq + (long long)i * Dc * HDc, HDc, 0, 0,
              pq, HDc, 0, 0, 1, Bc * Sc, HDc, Dc, 1,
              bq + i * HDc, nullptr, 0, 1.0f, nullptr, false);
        tgemm(px2, Dc, 0, 0, Wk + (long long)i * Dc * HDc, HDc, 0, 0,
              pk, HDc, 0, 0, 1, Bc * Sc, HDc, Dc, 1,
              bk + i * HDc, nullptr, 0, 1.0f, nullptr, false);
        tgemm(px2, Dc, 0, 0, Wv + (long long)i * Dc * HDc, HDc, 0, 0,
              pv, HDc, 0, 0, 1, Bc * Sc, HDc, Dc, 1,
              bv + i * HDc, nullptr, 0, 1.0f, nullptr, false);

        tgemm(pq, HDc, (long long)Sc * HDc, DKc,
              pk, HDc, (long long)Sc * HDc, DKc,
              ps, Sc, (long long)Hc * Sc * Sc, (long long)Sc * Sc,
              Hc, Sc, Sc, DKc, Bc * Hc,
              nullptr, nullptr, 0, iscale, attn_m, true);

        softmax_kernel<<<(Bc * Hc * Sc) / 8, 256>>>(ps);

        tgemm(ps, Sc, (long long)Hc * Sc * Sc, (long long)Sc * Sc,
              pv, HDc, (long long)Sc * HDc, DKc,
              po, HDc, (long long)Sc * HDc, DKc,
              Hc, Sc, DKc, Sc, Bc * Hc,
              nullptr, nullptr, 0, 1.0f, nullptr, false);

        tgemm(po, HDc, 0, 0, Wo + (long long)i * HDc * Dc, Dc, 0, 0,
              px, Dc, 0, 0, 1, Bc * Sc, Dc, HDc, 1,
              bo + i * Dc, px, 0, 1.0f, nullptr, false);

        layernorm_kernel<<<Bc * Sc, 128>>>(px, px2, alpha2 + i * Dc, bias2 + i * Dc);

        tgemm(px2, Dc, 0, 0, W1 + (long long)i * Dc * DFFc, DFFc, 0, 0,
              pf, DFFc, 0, 0, 1, Bc * Sc, DFFc, Dc, 1,
              b1 + i * DFFc, nullptr, 1, 1.0f, nullptr, false);

        tgemm(pf, DFFc, 0, 0, W2 + (long long)i * DFFc * Dc, Dc, 0, 0,
              px, Dc, 0, 0, 1, Bc * Sc, Dc, DFFc, 1,
              b2 + i * Dc, px, 0, 1.0f, nullptr, false);
    }

    layernorm_kernel<<<Bc * Sc, 128>>>(px, out, alphaf, biasf);
}

// round 3
// speedup vs baseline: 3.2071x; 1.3582x over previous
#include <cuda_runtime.h>
#include <math.h>
#include <stdint.h>

// ---------------- constants ----------------
#define Bc   8
#define Sc   256
#define Dc   512
#define Hc   8
#define DKc  256
#define HDc  2048
#define DFFc 2048
#define Lc   4

#define BSD  (Bc*Sc*Dc)
#define BSHD (Bc*Sc*HDc)
#define BHSS (Bc*Hc*Sc*Sc)
#define BSF  (Bc*Sc*DFFc)

// ---------------- scratch ----------------
__device__ __align__(16) float g_x [BSD];
__device__ __align__(16) float g_x2[BSD];
__device__ __align__(16) float g_q [BSHD];
__device__ __align__(16) float g_k [BSHD];
__device__ __align__(16) float g_v [BSHD];
__device__ __align__(16) float g_s [BHSS];
__device__ __align__(16) float g_o [BSHD];
__device__ __align__(16) float g_f [BSF];

// ---------------- embed ----------------
__global__ void embed_kernel(const float* __restrict__ data,
                             const float* __restrict__ seg,
                             const int*   __restrict__ view_idx,
                             float* __restrict__ x)
{
    int idx = blockIdx.x * blockDim.x + threadIdx.x;
    if (idx >= BSD) return;
    int d = idx & (Dc - 1);
    int s = (idx / Dc) & (Sc - 1);
    float angle = (float)s * exp2f(-(float)d * (1.0f / 32.0f));
    float pe = (d & 1) ? (float)cos((double)angle) : (float)sin((double)angle);
    int seg_row = view_idx[0] * Sc;
    x[idx] = data[idx] * 22.62741699796952f + pe + seg[seg_row * Dc + d];
}

// ---------------- layernorm (ddof=1, denom = sqrt(var)+eps) ----------------
__global__ void layernorm_kernel(const float* __restrict__ x, float* __restrict__ y,
                                 const float* __restrict__ alpha,
                                 const float* __restrict__ beta)
{
    int row = blockIdx.x;
    int t = threadIdx.x;
    const float4* xr = (const float4*)(x + (size_t)row * Dc);
    float4 v = xr[t];

    __shared__ float sh[4];
    float s = v.x + v.y + v.z + v.w;
    #pragma unroll
    for (int o = 16; o; o >>= 1) s += __shfl_xor_sync(0xFFFFFFFFu, s, o);
    if ((t & 31) == 0) sh[t >> 5] = s;
    __syncthreads();
    float mean = (sh[0] + sh[1] + sh[2] + sh[3]) * (1.0f / (float)Dc);

    float dx = v.x - mean, dy = v.y - mean, dz = v.z - mean, dw = v.w - mean;
    float q = dx*dx + dy*dy + dz*dz + dw*dw;
    __syncthreads();
    #pragma unroll
    for (int o = 16; o; o >>= 1) q += __shfl_xor_sync(0xFFFFFFFFu, q, o);
    if ((t & 31) == 0) sh[t >> 5] = q;
    __syncthreads();
    float var = (sh[0] + sh[1] + sh[2] + sh[3]) * (1.0f / (float)(Dc - 1));
    float inv = 1.0f / (sqrtf(var) + 1e-6f);

    float4 a = ((const float4*)alpha)[t];
    float4 b = ((const float4*)beta)[t];
    float4 o;
    o.x = a.x * dx * inv + b.x;
    o.y = a.y * dy * inv + b.y;
    o.z = a.z * dz * inv + b.z;
    o.w = a.w * dw * inv + b.w;
    ((float4*)(y + (size_t)row * Dc))[t] = o;
}

// ---------------- softmax ----------------
__global__ void softmax_kernel(float* __restrict__ s)
{
    int gw = (blockIdx.x * blockDim.x + threadIdx.x) >> 5;
    if (gw >= Bc * Hc * Sc) return;
    int lane = threadIdx.x & 31;
    float* r = s + (size_t)gw * Sc + lane * 8;
    float4 a = *(float4*)r;
    float4 b = *(float4*)(r + 4);
    float m = fmaxf(fmaxf(fmaxf(a.x, a.y), fmaxf(a.z, a.w)),
                    fmaxf(fmaxf(b.x, b.y), fmaxf(b.z, b.w)));
    #pragma unroll
    for (int o = 16; o; o >>= 1) m = fmaxf(m, __shfl_xor_sync(0xFFFFFFFFu, m, o));
    a.x = expf(a.x - m); a.y = expf(a.y - m); a.z = expf(a.z - m); a.w = expf(a.w - m);
    b.x = expf(b.x - m); b.y = expf(b.y - m); b.z = expf(b.z - m); b.w = expf(b.w - m);
    float sum = a.x + a.y + a.z + a.w + b.x + b.y + b.z + b.w;
    #pragma unroll
    for (int o = 16; o; o >>= 1) sum += __shfl_xor_sync(0xFFFFFFFFu, sum, o);
    float inv = 1.0f / sum;
    a.x *= inv; a.y *= inv; a.z *= inv; a.w *= inv;
    b.x *= inv; b.y *= inv; b.z *= inv; b.w *= inv;
    *(float4*)r = a;
    *(float4*)(r + 4) = b;
}

// ---------------- TF32 mma GEMM: 128x128 tile, BK=32, cp.async double buffer ------
#define APAD 36     // row-major k-contig tiles (A, and B when TRANSB)
#define BPAD 132    // k-major n-contig tile (B when !TRANSB)
#define ASTG (128*APAD)         // floats per A stage = 4608
#define BSTG_T (128*APAD)       // TRANSB B stage
#define BSTG_N (32*BPAD)        // !TRANSB B stage = 4224

__device__ __forceinline__ void cpa16(void* s, const void* g) {
    uint32_t sa = (uint32_t)__cvta_generic_to_shared(s);
    asm volatile("cp.async.cg.shared.global [%0], [%1], 16;" :: "r"(sa), "l"(g) : "memory");
}
__device__ __forceinline__ void cpa_commit() {
    asm volatile("cp.async.commit_group;" ::: "memory");
}
__device__ __forceinline__ void cpa_wait1() {
    asm volatile("cp.async.wait_group 1;" ::: "memory");
}

template<bool TRANSB>
__global__ __launch_bounds__(256, 2)
void tgemm_kernel(const float* __restrict__ A, int lda, long long sA0, long long sA1,
                  const float* __restrict__ Bp, int ldb, long long sB0, long long sB1,
                  float* __restrict__ C, int ldc, long long sC0, long long sC1,
                  int zdiv, int K,
                  const float* __restrict__ bias,
                  const float* __restrict__ residual,
                  int relu, float scale,
                  const int* __restrict__ mask)
{
    int z = blockIdx.z;
    int zb = z / zdiv, zi = z - zb * zdiv;
    A  += zb * sA0 + zi * sA1;
    Bp += zb * sB0 + zi * sB1;
    C  += zb * sC0 + zi * sC1;
    const float* res = residual ? residual + zb * sC0 + zi * sC1 : nullptr;

    extern __shared__ float sm[];
    float* As = sm;                 // 2 stages * ASTG
    float* Bs = sm + 2 * ASTG;
    constexpr int BSTG = TRANSB ? BSTG_T : BSTG_N;

    int tid = threadIdx.x;
    int lane = tid & 31, warp = tid >> 5;
    int wr = warp >> 2;        // 0..1
    int wc = warp & 3;         // 0..3
    int lr = lane >> 2;        // 0..7
    int lc = lane & 3;         // 0..3
    int mBase = wr * 64;
    int nBase = wc * 32;

    const float* Ag = A + (size_t)(blockIdx.y * 128) * lda;
    const float* Bg = TRANSB ? (Bp + (size_t)(blockIdx.x * 128) * ldb)
                             : (Bp + blockIdx.x * 128);

    float acc[4][4][4];
    #pragma unroll
    for (int i = 0; i < 4; i++)
        #pragma unroll
        for (int j = 0; j < 4; j++)
            #pragma unroll
            for (int k = 0; k < 4; k++) acc[i][j][k] = 0.0f;

    // stage loader
    auto load_stage = [&](int st, int kt) {
        int k0 = kt * 32;
        // A tile: 128 rows x 32 k
        #pragma unroll
        for (int i = 0; i < 4; i++) {
            int ch = tid + (i << 8);
            int r = ch & 127;
            int kc = ((ch >> 7) & 7) << 2;
            cpa16(&As[st * ASTG + r * APAD + kc], Ag + (size_t)r * lda + k0 + kc);
        }
        if (TRANSB) {
            #pragma unroll
            for (int i = 0; i < 4; i++) {
                int ch = tid + (i << 8);
                int r = ch & 127;
                int kc = ((ch >> 7) & 7) << 2;
                cpa16(&Bs[st * BSTG + r * APAD + kc], Bg + (size_t)r * ldb + k0 + kc);
            }
        } else {
            #pragma unroll
            for (int i = 0; i < 4; i++) {
                int ch = tid + (i << 8);
                int r = ch >> 5;            // 0..31 (k)
                int nc = (ch & 31) << 2;    // 0..124
                cpa16(&Bs[st * BSTG + r * BPAD + nc], Bg + (size_t)(k0 + r) * ldb + nc);
            }
        }
    };

    int kTiles = K >> 5;
    load_stage(0, 0);
    cpa_commit();
    if (kTiles > 1) load_stage(1, 1);
    cpa_commit();

    for (int kt = 0; kt < kTiles; kt++) {
        cpa_wait1();
        __syncthreads();
        int st = kt & 1;
        const float* Asb = As + st * ASTG;
        const float* Bsb = Bs + st * BSTG;

        #pragma unroll
        for (int kk = 0; kk < 32; kk += 8) {
            uint32_t af[4][4], bf[4][2];
            #pragma unroll
            for (int mt = 0; mt < 4; mt++) {
                const float* ap = Asb + (mBase + mt * 16 + lr) * APAD + kk + lc;
                af[mt][0] = __float_as_uint(ap[0]);
                af[mt][1] = __float_as_uint(ap[8 * APAD]);
                af[mt][2] = __float_as_uint(ap[4]);
                af[mt][3] = __float_as_uint(ap[8 * APAD + 4]);
            }
            #pragma unroll
            for (int nt = 0; nt < 4; nt++) {
                if (TRANSB) {
                    const float* bp = Bsb + (nBase + nt * 8 + lr) * APAD + kk + lc;
                    bf[nt][0] = __float_as_uint(bp[0]);
                    bf[nt][1] = __float_as_uint(bp[4]);
                } else {
                    const float* bp = Bsb + (kk + lc) * BPAD + nBase + nt * 8 + lr;
                    bf[nt][0] = __float_as_uint(bp[0]);
                    bf[nt][1] = __float_as_uint(bp[4 * BPAD]);
                }
            }
            #pragma unroll
            for (int mt = 0; mt < 4; mt++)
                #pragma unroll
                for (int nt = 0; nt < 4; nt++) {
                    asm volatile(
                        "mma.sync.aligned.m16n8k8.row.col.f32.tf32.tf32.f32 "
                        "{%0,%1,%2,%3}, {%4,%5,%6,%7}, {%8,%9}, {%0,%1,%2,%3};"
                        : "+f"(acc[mt][nt][0]), "+f"(acc[mt][nt][1]),
                          "+f"(acc[mt][nt][2]), "+f"(acc[mt][nt][3])
                        : "r"(af[mt][0]), "r"(af[mt][1]), "r"(af[mt][2]), "r"(af[mt][3]),
                          "r"(bf[nt][0]), "r"(bf[nt][1]));
                }
        }
        __syncthreads();
        if (kt + 2 < kTiles) load_stage(st, kt + 2);
        cpa_commit();
    }

    // ---------------- epilogue ----------------
    #pragma unroll
    for (int mt = 0; mt < 4; mt++) {
        #pragma unroll
        for (int nt = 0; nt < 4; nt++) {
            int row0 = blockIdx.y * 128 + mBase + mt * 16 + lr;
            int col  = blockIdx.x * 128 + nBase + nt * 8 + lc * 2;
            float b0 = bias ? bias[col]     : 0.0f;
            float b1 = bias ? bias[col + 1] : 0.0f;
            int m0 = mask ? mask[zb * Sc + col]     : 0;
            int m1 = mask ? mask[zb * Sc + col + 1] : 0;
            #pragma unroll
            for (int h = 0; h < 2; h++) {
                int row = row0 + h * 8;
                float c0 = acc[mt][nt][h * 2 + 0] + b0;
                float c1 = acc[mt][nt][h * 2 + 1] + b1;
                c0 *= scale; c1 *= scale;
                if (mask) { if (m0) c0 = -1e9f; if (m1) c1 = -1e9f; }
                if (relu) { c0 = fmaxf(c0, 0.0f); c1 = fmaxf(c1, 0.0f); }
                size_t off = (size_t)row * ldc + col;
                if (res) {
                    float2 r2 = *(const float2*)(res + off);
                    c0 += r2.x; c1 += r2.y;
                }
                *(float2*)(C + off) = make_float2(c0, c1);
            }
        }
    }
}

#define SMEM_T ((2*ASTG + 2*BSTG_T) * 4)
#define SMEM_N ((2*ASTG + 2*BSTG_N) * 4)

// ---------------- host-side helper ----------------
static void tgemm(const float* A, int lda, long long sA0, long long sA1,
                  const float* B, int ldb, long long sB0, long long sB1,
                  float* C, int ldc, long long sC0, long long sC1,
                  int zdiv, int M, int N, int K, int nz,
                  const float* bias, const float* res, int relu, float scale,
                  const int* mask, bool transb)
{
    dim3 grid(N / 128, M / 128, nz), block(256);
    if (transb) {
        cudaFuncSetAttribute(tgemm_kernel<true>,
                             cudaFuncAttributeMaxDynamicSharedMemorySize, SMEM_T);
        tgemm_kernel<true><<<grid, block, SMEM_T>>>(A, lda, sA0, sA1, B, ldb, sB0, sB1,
                                                    C, ldc, sC0, sC1, zdiv, K,
                                                    bias, res, relu, scale, mask);
    } else {
        cudaFuncSetAttribute(tgemm_kernel<false>,
                             cudaFuncAttributeMaxDynamicSharedMemorySize, SMEM_N);
        tgemm_kernel<false><<<grid, block, SMEM_N>>>(A, lda, sA0, sA1, B, ldb, sB0, sB1,
                                                     C, ldc, sC0, sC1, zdiv, K,
                                                     bias, res, relu, scale, mask);
    }
}

extern "C" void kernel_launch(void* const* d_in, const int* in_sizes, int n_in,
                              void* d_out, int out_size)
{
    const float* data    = (const float*)d_in[0];
    const int*   attn_m  = (const int*)  d_in[1];
    const int*   view_ix = (const int*)  d_in[2];
    const float* seg     = (const float*)d_in[3];
    const float* Wq = (const float*)d_in[4];
    const float* bq = (const float*)d_in[5];
    const float* Wk = (const float*)d_in[6];
    const float* bk = (const float*)d_in[7];
    const float* Wv = (const float*)d_in[8];
    const float* bv = (const float*)d_in[9];
    const float* Wo = (const float*)d_in[10];
    const float* bo = (const float*)d_in[11];
    const float* W1 = (const float*)d_in[12];
    const float* b1 = (const float*)d_in[13];
    const float* W2 = (const float*)d_in[14];
    const float* b2 = (const float*)d_in[15];
    const float* alpha1 = (const float*)d_in[16];
    const float* bias1  = (const float*)d_in[17];
    const float* alpha2 = (const float*)d_in[18];
    const float* bias2  = (const float*)d_in[19];
    const float* alphaf = (const float*)d_in[20];
    const float* biasf  = (const float*)d_in[21];
    float* out = (float*)d_out;

    static float *px = nullptr, *px2, *pq, *pk, *pv, *ps, *po, *pf;
    if (!px) {
        cudaGetSymbolAddress((void**)&px,  g_x);
        cudaGetSymbolAddress((void**)&px2, g_x2);
        cudaGetSymbolAddress((void**)&pq,  g_q);
        cudaGetSymbolAddress((void**)&pk,  g_k);
        cudaGetSymbolAddress((void**)&pv,  g_v);
        cudaGetSymbolAddress((void**)&ps,  g_s);
        cudaGetSymbolAddress((void**)&po,  g_o);
        cudaGetSymbolAddress((void**)&pf,  g_f);
    }

    const float iscale = 0.0625f;

    embed_kernel<<<(BSD + 255) / 256, 256>>>(data, seg, view_ix, px);

    for (int i = 0; i < Lc; i++) {
        layernorm_kernel<<<Bc * Sc, 128>>>(px, px2, alpha1 + i * Dc, bias1 + i * Dc);

        tgemm(px2, Dc, 0, 0, Wq + (long long)i * Dc * HDc, HDc, 0, 0,
              pq, HDc, 0, 0, 1, Bc * Sc, HDc, Dc, 1,
              bq + i * HDc, nullptr, 0, 1.0f, nullptr, false);
        tgemm(px2, Dc, 0, 0, Wk + (long long)i * Dc * HDc, HDc, 0, 0,
              pk, HDc, 0, 0, 1, Bc * Sc, HDc, Dc, 1,
              bk + i * HDc, nullptr, 0, 1.0f, nullptr, false);
        tgemm(px2, Dc, 0, 0, Wv + (long long)i * Dc * HDc, HDc, 0, 0,
              pv, HDc, 0, 0, 1, Bc * Sc, HDc, Dc, 1,
              bv + i * HDc, nullptr, 0, 1.0f, nullptr, false);

        tgemm(pq, HDc, (long long)Sc * HDc, DKc,
              pk, HDc, (long long)Sc * HDc, DKc,
              ps, Sc, (long long)Hc * Sc * Sc, (long long)Sc * Sc,
              Hc, Sc, Sc, DKc, Bc * Hc,
              nullptr, nullptr, 0, iscale, attn_m, true);

        softmax_kernel<<<(Bc * Hc * Sc) / 8, 256>>>(ps);

        tgemm(ps, Sc, (long long)Hc * Sc * Sc, (long long)Sc * Sc,
              pv, HDc, (long long)Sc * HDc, DKc,
              po, HDc, (long long)Sc * HDc, DKc,
              Hc, Sc, DKc, Sc, Bc * Hc,
              nullptr, nullptr, 0, 1.0f, nullptr, false);

        tgemm(po, HDc, 0, 0, Wo + (long long)i * HDc * Dc, Dc, 0, 0,
              px, Dc, 0, 0, 1, Bc * Sc, Dc, HDc, 1,
              bo + i * Dc, px, 0, 1.0f, nullptr, false);

        layernorm_kernel<<<Bc * Sc, 128>>>(px, px2, alpha2 + i * Dc, bias2 + i * Dc);

        tgemm(px2, Dc, 0, 0, W1 + (long long)i * Dc * DFFc, DFFc, 0, 0,
              pf, DFFc, 0, 0, 1, Bc * Sc, DFFc, Dc, 1,
              b1 + i * DFFc, nullptr, 1, 1.0f, nullptr, false);

        tgemm(pf, DFFc, 0, 0, W2 + (long long)i * DFFc * Dc, Dc, 0, 0,
              px, Dc, 0, 0, 1, Bc * Sc, Dc, DFFc, 1,
              b2 + i * Dc, px, 0, 1.0f, nullptr, false);
    }

    layernorm_kernel<<<Bc * Sc, 128>>>(px, out, alphaf, biasf);
}

// round 4
// speedup vs baseline: 8.3693x; 2.6096x over previous
#include <cuda_runtime.h>
#include <cuda_bf16.h>
#include <math.h>
#include <stdint.h>

// ---------------- constants ----------------
#define Bc   8
#define Sc   256
#define Dc   512
#define Hc   8
#define DKc  256
#define HDc  2048
#define DFFc 2048
#define Lc   4

#define BSD  (Bc*Sc*Dc)      // 1M
#define BSHD (Bc*Sc*HDc)     // 4M
#define BHSS (Bc*Hc*Sc*Sc)   // 4M
#define BSF  (Bc*Sc*DFFc)    // 4M
#define WSZ  (Dc*HDc)        // 1M per layer per weight

// ---------------- scratch ----------------
__device__ __align__(16) float g_x   [BSD];
__device__ __align__(16) float g_s   [BHSS];
__device__ __align__(16) float g_part[4*BSD];       // split-K partials (2048x512 x4)
__device__ __align__(16) __nv_bfloat16 g_x2b[BSD];
__device__ __align__(16) __nv_bfloat16 g_qb [BSHD];
__device__ __align__(16) __nv_bfloat16 g_kb [BSHD];
__device__ __align__(16) __nv_bfloat16 g_vb [BSHD];
__device__ __align__(16) __nv_bfloat16 g_ob [BSHD];
__device__ __align__(16) __nv_bfloat16 g_pb [BHSS];
__device__ __align__(16) __nv_bfloat16 g_fb [BSF];
__device__ __align__(16) __nv_bfloat16 g_wq [Lc*WSZ];
__device__ __align__(16) __nv_bfloat16 g_wk [Lc*WSZ];
__device__ __align__(16) __nv_bfloat16 g_wv [Lc*WSZ];
__device__ __align__(16) __nv_bfloat16 g_wo [Lc*WSZ];
__device__ __align__(16) __nv_bfloat16 g_w1 [Lc*WSZ];
__device__ __align__(16) __nv_bfloat16 g_w2 [Lc*WSZ];

// ---------------- fp32 -> bf16 convert ----------------
__global__ void f2b_kernel(const float* __restrict__ in,
                           __nv_bfloat16* __restrict__ out, int n4)
{
    int i = blockIdx.x * blockDim.x + threadIdx.x;
    if (i >= n4) return;
    float4 v = ((const float4*)in)[i];
    __nv_bfloat162 lo, hi;
    lo.x = __float2bfloat16_rn(v.x); lo.y = __float2bfloat16_rn(v.y);
    hi.x = __float2bfloat16_rn(v.z); hi.y = __float2bfloat16_rn(v.w);
    ((__nv_bfloat162*)out)[2*i]   = lo;
    ((__nv_bfloat162*)out)[2*i+1] = hi;
}

// ---------------- embed ----------------
__global__ void embed_kernel(const float* __restrict__ data,
                             const float* __restrict__ seg,
                             const int*   __restrict__ view_idx,
                             float* __restrict__ x)
{
    int idx = blockIdx.x * blockDim.x + threadIdx.x;
    if (idx >= BSD) return;
    int d = idx & (Dc - 1);
    int s = (idx / Dc) & (Sc - 1);
    float angle = (float)s * exp2f(-(float)d * (1.0f / 32.0f));
    float pe = (d & 1) ? (float)cos((double)angle) : (float)sin((double)angle);
    int seg_row = view_idx[0] * Sc;
    x[idx] = data[idx] * 22.62741699796952f + pe + seg[seg_row * Dc + d];
}

// ---------------- LN helpers ----------------
__device__ __forceinline__ float2 ln_stats(float4 v, int t, float* sh)
{
    float s = v.x + v.y + v.z + v.w;
    #pragma unroll
    for (int o = 16; o; o >>= 1) s += __shfl_xor_sync(0xFFFFFFFFu, s, o);
    if ((t & 31) == 0) sh[t >> 5] = s;
    __syncthreads();
    float mean = (sh[0] + sh[1] + sh[2] + sh[3]) * (1.0f / (float)Dc);
    float dx = v.x - mean, dy = v.y - mean, dz = v.z - mean, dw = v.w - mean;
    float q = dx*dx + dy*dy + dz*dz + dw*dw;
    __syncthreads();
    #pragma unroll
    for (int o = 16; o; o >>= 1) q += __shfl_xor_sync(0xFFFFFFFFu, q, o);
    if ((t & 31) == 0) sh[t >> 5] = q;
    __syncthreads();
    float var = (sh[0] + sh[1] + sh[2] + sh[3]) * (1.0f / (float)(Dc - 1));
    float inv = 1.0f / (sqrtf(var) + 1e-6f);
    return make_float2(mean, inv);
}

// plain LN, fp32 in -> bf16 out
__global__ void ln_bf16_kernel(const float* __restrict__ x,
                               __nv_bfloat16* __restrict__ y,
                               const float* __restrict__ alpha,
                               const float* __restrict__ beta)
{
    int row = blockIdx.x, t = threadIdx.x;
    __shared__ float sh[4];
    float4 v = ((const float4*)(x + (size_t)row * Dc))[t];
    float2 mi = ln_stats(v, t, sh);
    float4 a = ((const float4*)alpha)[t];
    float4 b = ((const float4*)beta)[t];
    __nv_bfloat162 o0, o1;
    o0.x = __float2bfloat16_rn(a.x * (v.x - mi.x) * mi.y + b.x);
    o0.y = __float2bfloat16_rn(a.y * (v.y - mi.x) * mi.y + b.y);
    o1.x = __float2bfloat16_rn(a.z * (v.z - mi.x) * mi.y + b.z);
    o1.y = __float2bfloat16_rn(a.w * (v.w - mi.x) * mi.y + b.w);
    __nv_bfloat162* yr = (__nv_bfloat162*)(y + (size_t)row * Dc);
    yr[2*t] = o0; yr[2*t+1] = o1;
}

// fused: x += sum(partials) + bias ; then LN -> bf16 (ybf) or fp32 (yf)
__global__ void reduce_ln_kernel(const float* __restrict__ part,
                                 const float* __restrict__ bias,
                                 float* __restrict__ x,
                                 const float* __restrict__ alpha,
                                 const float* __restrict__ beta,
                                 __nv_bfloat16* __restrict__ ybf,
                                 float* __restrict__ yf)
{
    int row = blockIdx.x, t = threadIdx.x;
    __shared__ float sh[4];
    size_t off = (size_t)row * Dc + t * 4;
    float4 v = *(const float4*)(x + off);
    #pragma unroll
    for (int s = 0; s < 4; s++) {
        float4 p = *(const float4*)(part + (size_t)s * BSD + off);
        v.x += p.x; v.y += p.y; v.z += p.z; v.w += p.w;
    }
    float4 b4 = ((const float4*)bias)[t];
    v.x += b4.x; v.y += b4.y; v.z += b4.z; v.w += b4.w;
    *(float4*)(x + off) = v;

    float2 mi = ln_stats(v, t, sh);
    float4 a = ((const float4*)alpha)[t];
    float4 bb = ((const float4*)beta)[t];
    float y0 = a.x * (v.x - mi.x) * mi.y + bb.x;
    float y1 = a.y * (v.y - mi.x) * mi.y + bb.y;
    float y2 = a.z * (v.z - mi.x) * mi.y + bb.z;
    float y3 = a.w * (v.w - mi.x) * mi.y + bb.w;
    if (ybf) {
        __nv_bfloat162 o0, o1;
        o0.x = __float2bfloat16_rn(y0); o0.y = __float2bfloat16_rn(y1);
        o1.x = __float2bfloat16_rn(y2); o1.y = __float2bfloat16_rn(y3);
        __nv_bfloat162* yr = (__nv_bfloat162*)(ybf + (size_t)row * Dc);
        yr[2*t] = o0; yr[2*t+1] = o1;
    } else {
        *(float4*)(yf + off) = make_float4(y0, y1, y2, y3);
    }
}

// ---------------- softmax: fp32 scores -> bf16 probs ----------------
__global__ void softmax_kernel(const float* __restrict__ s,
                               __nv_bfloat16* __restrict__ p)
{
    int gw = (blockIdx.x * blockDim.x + threadIdx.x) >> 5;
    if (gw >= Bc * Hc * Sc) return;
    int lane = threadIdx.x & 31;
    const float* r = s + (size_t)gw * Sc + lane * 8;
    float4 a = *(const float4*)r;
    float4 b = *(const float4*)(r + 4);
    float m = fmaxf(fmaxf(fmaxf(a.x, a.y), fmaxf(a.z, a.w)),
                    fmaxf(fmaxf(b.x, b.y), fmaxf(b.z, b.w)));
    #pragma unroll
    for (int o = 16; o; o >>= 1) m = fmaxf(m, __shfl_xor_sync(0xFFFFFFFFu, m, o));
    a.x = expf(a.x - m); a.y = expf(a.y - m); a.z = expf(a.z - m); a.w = expf(a.w - m);
    b.x = expf(b.x - m); b.y = expf(b.y - m); b.z = expf(b.z - m); b.w = expf(b.w - m);
    float sum = a.x + a.y + a.z + a.w + b.x + b.y + b.z + b.w;
    #pragma unroll
    for (int o = 16; o; o >>= 1) sum += __shfl_xor_sync(0xFFFFFFFFu, sum, o);
    float inv = 1.0f / sum;
    __nv_bfloat162* o2 = (__nv_bfloat162*)(p + (size_t)gw * Sc + lane * 8);
    __nv_bfloat162 h;
    h.x = __float2bfloat16_rn(a.x * inv); h.y = __float2bfloat16_rn(a.y * inv); o2[0] = h;
    h.x = __float2bfloat16_rn(a.z * inv); h.y = __float2bfloat16_rn(a.w * inv); o2[1] = h;
    h.x = __float2bfloat16_rn(b.x * inv); h.y = __float2bfloat16_rn(b.y * inv); o2[2] = h;
    h.x = __float2bfloat16_rn(b.z * inv); h.y = __float2bfloat16_rn(b.w * inv); o2[3] = h;
}

// ---------------- bf16 MMA GEMM: 128x128 tile, BK=32, cp.async, ldmatrix ----------
#define APADh 40      // halves pitch for k-contig tiles (A, B when TRANSB)
#define BPADh 136     // halves pitch for [k][n] tile (B when !TRANSB)
#define ASTGh (128*APADh)     // 5120 halves / stage
#define BSTGh_T (128*APADh)
#define BSTGh_N (32*BPADh)    // 4352

__device__ __forceinline__ void cpa16(void* s, const void* g) {
    uint32_t sa = (uint32_t)__cvta_generic_to_shared(s);
    asm volatile("cp.async.cg.shared.global [%0], [%1], 16;" :: "r"(sa), "l"(g) : "memory");
}
__device__ __forceinline__ void cpa_commit() {
    asm volatile("cp.async.commit_group;" ::: "memory");
}
__device__ __forceinline__ void cpa_wait1() {
    asm volatile("cp.async.wait_group 1;" ::: "memory");
}
__device__ __forceinline__ void ldsm4(uint32_t& r0, uint32_t& r1, uint32_t& r2, uint32_t& r3, uint32_t a) {
    asm volatile("ldmatrix.sync.aligned.m8n8.x4.shared.b16 {%0,%1,%2,%3}, [%4];"
                 : "=r"(r0), "=r"(r1), "=r"(r2), "=r"(r3) : "r"(a));
}
__device__ __forceinline__ void ldsm4t(uint32_t& r0, uint32_t& r1, uint32_t& r2, uint32_t& r3, uint32_t a) {
    asm volatile("ldmatrix.sync.aligned.m8n8.x4.trans.shared.b16 {%0,%1,%2,%3}, [%4];"
                 : "=r"(r0), "=r"(r1), "=r"(r2), "=r"(r3) : "r"(a));
}

template<bool TRANSB>
__global__ __launch_bounds__(256, 2)
void bgemm_kernel(const __nv_bfloat16* __restrict__ A, int lda, long long sA0, long long sA1,
                  const __nv_bfloat16* __restrict__ Bp, int ldb, long long sB0, long long sB1,
                  void* __restrict__ Cv, int ldc, long long sC0, long long sC1,
                  int zdiv, int K,
                  const float* __restrict__ bias,
                  int relu, float scale,
                  const int* __restrict__ mask, int outbf)
{
    int z = blockIdx.z;
    int zb = z / zdiv, zi = z - zb * zdiv;
    A  += zb * sA0 + zi * sA1;
    Bp += zb * sB0 + zi * sB1;
    size_t coff = (size_t)zb * sC0 + (size_t)zi * sC1;

    extern __shared__ __nv_bfloat16 sm[];
    __nv_bfloat16* As = sm;
    __nv_bfloat16* Bs = sm + 2 * ASTGh;
    constexpr int BSTG = TRANSB ? BSTGh_T : BSTGh_N;

    int tid = threadIdx.x;
    int lane = tid & 31, warp = tid >> 5;
    int mBase = (warp >> 2) * 64;
    int nBase = (warp & 3) * 32;
    int lr = lane >> 2, lc = lane & 3;

    const __nv_bfloat16* Ag = A + (size_t)(blockIdx.y * 128) * lda;
    const __nv_bfloat16* Bg = TRANSB ? (Bp + (size_t)(blockIdx.x * 128) * ldb)
                                     : (Bp + blockIdx.x * 128);

    float acc[4][4][4];
    #pragma unroll
    for (int i = 0; i < 4; i++)
        #pragma unroll
        for (int j = 0; j < 4; j++)
            #pragma unroll
            for (int k = 0; k < 4; k++) acc[i][j][k] = 0.0f;

    auto load_stage = [&](int st, int kt) {
        int k0 = kt * 32;
        #pragma unroll
        for (int i = 0; i < 2; i++) {
            int ch = tid + (i << 8);
            int r = ch >> 2, c = (ch & 3) << 3;
            cpa16(&As[st * ASTGh + r * APADh + c], Ag + (size_t)r * lda + k0 + c);
        }
        if (TRANSB) {
            #pragma unroll
            for (int i = 0; i < 2; i++) {
                int ch = tid + (i << 8);
                int r = ch >> 2, c = (ch & 3) << 3;
                cpa16(&Bs[st * BSTG + r * APADh + c], Bg + (size_t)r * ldb + k0 + c);
            }
        } else {
            #pragma unroll
            for (int i = 0; i < 2; i++) {
                int ch = tid + (i << 8);
                int r = ch >> 4, c = (ch & 15) << 3;
                cpa16(&Bs[st * BSTG + r * BPADh + c], Bg + (size_t)(k0 + r) * ldb + c);
            }
        }
    };

    // precomputed fragment offsets (in halves, before kk)
    uint32_t aBase = (uint32_t)__cvta_generic_to_shared(As);
    uint32_t bBase = (uint32_t)__cvta_generic_to_shared(Bs);
    int aRow[4];
    #pragma unroll
    for (int mt = 0; mt < 4; mt++)
        aRow[mt] = (mBase + mt * 16 + (lane & 15)) * APADh + ((lane >> 4) << 3);
    int bRow[2];
    #pragma unroll
    for (int p = 0; p < 2; p++) {
        if (TRANSB)
            bRow[p] = (nBase + p * 16 + (lane & 7) + (((lane >> 4) & 1) << 3)) * APADh
                      + (((lane >> 3) & 1) << 3);
        else
            bRow[p] = ((lane & 7) + (((lane >> 3) & 1) << 3)) * BPADh
                      + nBase + p * 16 + (((lane >> 4) & 1) << 3);
    }

    int kTiles = K >> 5;
    load_stage(0, 0);
    cpa_commit();
    if (kTiles > 1) load_stage(1, 1);
    cpa_commit();

    for (int kt = 0; kt < kTiles; kt++) {
        cpa_wait1();
        __syncthreads();
        int st = kt & 1;
        uint32_t aS = aBase + st * (ASTGh * 2);
        uint32_t bS = bBase + st * (BSTG * 2);

        #pragma unroll
        for (int kk = 0; kk < 32; kk += 16) {
            uint32_t af[4][4], bf[4][2];
            #pragma unroll
            for (int mt = 0; mt < 4; mt++)
                ldsm4(af[mt][0], af[mt][1], af[mt][2], af[mt][3],
                      aS + 2 * (aRow[mt] + kk));
            #pragma unroll
            for (int p = 0; p < 2; p++) {
                if (TRANSB)
                    ldsm4(bf[2*p][0], bf[2*p][1], bf[2*p+1][0], bf[2*p+1][1],
                          bS + 2 * (bRow[p] + kk));
                else
                    ldsm4t(bf[2*p][0], bf[2*p][1], bf[2*p+1][0], bf[2*p+1][1],
                           bS + 2 * (bRow[p] + kk * BPADh));
            }
            #pragma unroll
            for (int mt = 0; mt < 4; mt++)
                #pragma unroll
                for (int nt = 0; nt < 4; nt++) {
                    asm volatile(
                        "mma.sync.aligned.m16n8k16.row.col.f32.bf16.bf16.f32 "
                        "{%0,%1,%2,%3}, {%4,%5,%6,%7}, {%8,%9}, {%0,%1,%2,%3};"
                        : "+f"(acc[mt][nt][0]), "+f"(acc[mt][nt][1]),
                          "+f"(acc[mt][nt][2]), "+f"(acc[mt][nt][3])
                        : "r"(af[mt][0]), "r"(af[mt][1]), "r"(af[mt][2]), "r"(af[mt][3]),
                          "r"(bf[nt][0]), "r"(bf[nt][1]));
                }
        }
        __syncthreads();
        if (kt + 2 < kTiles) load_stage(st, kt + 2);
        cpa_commit();
    }

    // ---------------- epilogue ----------------
    float* Cf = (float*)Cv + coff;
    __nv_bfloat16* Cb = (__nv_bfloat16*)Cv + coff;
    #pragma unroll
    for (int mt = 0; mt < 4; mt++) {
        #pragma unroll
        for (int nt = 0; nt < 4; nt++) {
            int row0 = blockIdx.y * 128 + mBase + mt * 16 + lr;
            int col  = blockIdx.x * 128 + nBase + nt * 8 + lc * 2;
            float b0 = bias ? bias[col]     : 0.0f;
            float b1 = bias ? bias[col + 1] : 0.0f;
            int m0 = mask ? mask[zb * Sc + col]     : 0;
            int m1 = mask ? mask[zb * Sc + col + 1] : 0;
            #pragma unroll
            for (int h = 0; h < 2; h++) {
                int row = row0 + h * 8;
                float c0 = acc[mt][nt][h * 2 + 0] + b0;
                float c1 = acc[mt][nt][h * 2 + 1] + b1;
                c0 *= scale; c1 *= scale;
                if (mask) { if (m0) c0 = -1e9f; if (m1) c1 = -1e9f; }
                if (relu) { c0 = fmaxf(c0, 0.0f); c1 = fmaxf(c1, 0.0f); }
                size_t off = (size_t)row * ldc + col;
                if (outbf) {
                    __nv_bfloat162 h2;
                    h2.x = __float2bfloat16_rn(c0);
                    h2.y = __float2bfloat16_rn(c1);
                    *(__nv_bfloat162*)(Cb + off) = h2;
                } else {
                    *(float2*)(Cf + off) = make_float2(c0, c1);
                }
            }
        }
    }
}

#define SMEM_BT ((2*ASTGh + 2*BSTGh_T) * 2)
#define SMEM_BN ((2*ASTGh + 2*BSTGh_N) * 2)

static void bgemm(const __nv_bfloat16* A, int lda, long long sA0, long long sA1,
                  const __nv_bfloat16* B, int ldb, long long sB0, long long sB1,
                  void* C, int ldc, long long sC0, long long sC1,
                  int zdiv, int M, int N, int K, int nz,
                  const float* bias, int relu, float scale,
                  const int* mask, int outbf, bool transb)
{
    dim3 grid(N / 128, M / 128, nz), block(256);
    if (transb)
        bgemm_kernel<true><<<grid, block, SMEM_BT>>>(A, lda, sA0, sA1, B, ldb, sB0, sB1,
                                                     C, ldc, sC0, sC1, zdiv, K,
                                                     bias, relu, scale, mask, outbf);
    else
        bgemm_kernel<false><<<grid, block, SMEM_BN>>>(A, lda, sA0, sA1, B, ldb, sB0, sB1,
                                                      C, ldc, sC0, sC1, zdiv, K,
                                                      bias, relu, scale, mask, outbf);
}

extern "C" void kernel_launch(void* const* d_in, const int* in_sizes, int n_in,
                              void* d_out, int out_size)
{
    const float* data    = (const float*)d_in[0];
    const int*   attn_m  = (const int*)  d_in[1];
    const int*   view_ix = (const int*)  d_in[2];
    const float* seg     = (const float*)d_in[3];
    const float* Wq = (const float*)d_in[4];
    const float* bq = (const float*)d_in[5];
    const float* Wk = (const float*)d_in[6];
    const float* bk = (const float*)d_in[7];
    const float* Wv = (const float*)d_in[8];
    const float* bv = (const float*)d_in[9];
    const float* Wo = (const float*)d_in[10];
    const float* bo = (const float*)d_in[11];
    const float* W1 = (const float*)d_in[12];
    const float* b1 = (const float*)d_in[13];
    const float* W2 = (const float*)d_in[14];
    const float* b2 = (const float*)d_in[15];
    const float* alpha1 = (const float*)d_in[16];
    const float* bias1  = (const float*)d_in[17];
    const float* alpha2 = (const float*)d_in[18];
    const float* bias2  = (const float*)d_in[19];
    const float* alphaf = (const float*)d_in[20];
    const float* biasf  = (const float*)d_in[21];
    float* out = (float*)d_out;

    static float *px = nullptr, *ps, *ppart;
    static __nv_bfloat16 *px2b, *pqb, *pkb, *pvb, *pob, *ppb, *pfb;
    static __nv_bfloat16 *wq, *wk, *wv, *wo, *w1, *w2;
    if (!px) {
        cudaGetSymbolAddress((void**)&px,    g_x);
        cudaGetSymbolAddress((void**)&ps,    g_s);
        cudaGetSymbolAddress((void**)&ppart, g_part);
        cudaGetSymbolAddress((void**)&px2b,  g_x2b);
        cudaGetSymbolAddress((void**)&pqb,   g_qb);
        cudaGetSymbolAddress((void**)&pkb,   g_kb);
        cudaGetSymbolAddress((void**)&pvb,   g_vb);
        cudaGetSymbolAddress((void**)&pob,   g_ob);
        cudaGetSymbolAddress((void**)&ppb,   g_pb);
        cudaGetSymbolAddress((void**)&pfb,   g_fb);
        cudaGetSymbolAddress((void**)&wq,    g_wq);
        cudaGetSymbolAddress((void**)&wk,    g_wk);
        cudaGetSymbolAddress((void**)&wv,    g_wv);
        cudaGetSymbolAddress((void**)&wo,    g_wo);
        cudaGetSymbolAddress((void**)&w1,    g_w1);
        cudaGetSymbolAddress((void**)&w2,    g_w2);
    }

    // weight conversion (each invocation; graph-capturable)
    {
        int n4 = Lc * WSZ / 4, nb = (n4 + 255) / 256;
        f2b_kernel<<<nb, 256>>>(Wq, wq, n4);
        f2b_kernel<<<nb, 256>>>(Wk, wk, n4);
        f2b_kernel<<<nb, 256>>>(Wv, wv, n4);
        f2b_kernel<<<nb, 256>>>(Wo, wo, n4);
        f2b_kernel<<<nb, 256>>>(W1, w1, n4);
        f2b_kernel<<<nb, 256>>>(W2, w2, n4);
    }

    embed_kernel<<<(BSD + 255) / 256, 256>>>(data, seg, view_ix, px);
    ln_bf16_kernel<<<Bc * Sc, 128>>>(px, px2b, alpha1, bias1);

    const float iscale = 0.0625f;

    for (int i = 0; i < Lc; i++) {
        // QKV: [2048,512]@[512,2048] -> bf16
        bgemm(px2b, Dc, 0, 0, wq + (long long)i * WSZ, HDc, 0, 0,
              pqb, HDc, 0, 0, 1, Bc * Sc, HDc, Dc, 1,
              bq + i * HDc, 0, 1.0f, nullptr, 1, false);
        bgemm(px2b, Dc, 0, 0, wk + (long long)i * WSZ, HDc, 0, 0,
              pkb, HDc, 0, 0, 1, Bc * Sc, HDc, Dc, 1,
              bk + i * HDc, 0, 1.0f, nullptr, 1, false);
        bgemm(px2b, Dc, 0, 0, wv + (long long)i * WSZ, HDc, 0, 0,
              pvb, HDc, 0, 0, 1, Bc * Sc, HDc, Dc, 1,
              bv + i * HDc, 0, 1.0f, nullptr, 1, false);

        // scores = Q @ K^T * 1/16, masked -> fp32
        bgemm(pqb, HDc, (long long)Sc * HDc, DKc,
              pkb, HDc, (long long)Sc * HDc, DKc,
              ps, Sc, (long long)Hc * Sc * Sc, (long long)Sc * Sc,
              Hc, Sc, Sc, DKc, Bc * Hc,
              nullptr, 0, iscale, attn_m, 0, true);

        softmax_kernel<<<(Bc * Hc * Sc) / 8, 256>>>(ps, ppb);

        // o = P @ V -> bf16 in [B,S,H*DK]
        bgemm(ppb, Sc, (long long)Hc * Sc * Sc, (long long)Sc * Sc,
              pvb, HDc, (long long)Sc * HDc, DKc,
              pob, HDc, (long long)Sc * HDc, DKc,
              Hc, Sc, DKc, Sc, Bc * Hc,
              nullptr, 0, 1.0f, nullptr, 1, false);

        // Wo: split-K=4 partials
        bgemm(pob, HDc, 0, DKc * 2,              // A k-offset per split: 512 halves
              wo + (long long)i * WSZ, Dc, 0, (long long)512 * Dc,
              ppart, Dc, 0, (long long)BSD,
              4, Bc * Sc, Dc, HDc / 4, 4,
              nullptr, 0, 1.0f, nullptr, 0, false);
        reduce_ln_kernel<<<Bc * Sc, 128>>>(ppart, bo + i * Dc, px,
                                           alpha2 + i * Dc, bias2 + i * Dc,
                                           px2b, nullptr);

        // ff = relu(x2 @ W1 + b1) -> bf16
        bgemm(px2b, Dc, 0, 0, w1 + (long long)i * WSZ, DFFc, 0, 0,
              pfb, DFFc, 0, 0, 1, Bc * Sc, DFFc, Dc, 1,
              b1 + i * DFFc, 1, 1.0f, nullptr, 1, false);

        // W2: split-K=4 partials
        bgemm(pfb, DFFc, 0, DKc * 2,
              w2 + (long long)i * WSZ, Dc, 0, (long long)512 * Dc,
              ppart, Dc, 0, (long long)BSD,
              4, Bc * Sc, Dc, DFFc / 4, 4,
              nullptr, 0, 1.0f, nullptr, 0, false);

        if (i < Lc - 1)
            reduce_ln_kernel<<<Bc * Sc, 128>>>(ppart, b2 + i * Dc, px,
                                               alpha1 + (i + 1) * Dc, bias1 + (i + 1) * Dc,
                                               px2b, nullptr);
        else
            reduce_ln_kernel<<<Bc * Sc, 128>>>(ppart, b2 + i * Dc, px,
                                               alphaf, biasf,
                                               nullptr, out);
    }
}

// round 5
// speedup vs baseline: 8.6427x; 1.0327x over previous
#include <cuda_runtime.h>
#include <cuda_bf16.h>
#include <math.h>
#include <stdint.h>

// ---------------- constants ----------------
#define Bc   8
#define Sc   256
#define Dc   512
#define Hc   8
#define DKc  256
#define HDc  2048
#define DFFc 2048
#define Lc   4
#define NQKV 6144   // 3*HD

#define BSD  (Bc*Sc*Dc)      // 1M
#define BSHD (Bc*Sc*HDc)     // 4M
#define BHSS (Bc*Hc*Sc*Sc)   // 4M
#define BSF  (Bc*Sc*DFFc)    // 4M
#define WSZ  (Dc*HDc)        // 1M

// ---------------- scratch ----------------
__device__ __align__(16) float g_x   [BSD];
__device__ __align__(16) float g_s   [BHSS];
__device__ __align__(16) float g_part[4*BSD];
__device__ __align__(16) float g_bqkv[Lc*NQKV];
__device__ __align__(16) __nv_bfloat16 g_x2b [BSD];
__device__ __align__(16) __nv_bfloat16 g_qkvb[Bc*Sc*NQKV];   // fused QKV output
__device__ __align__(16) __nv_bfloat16 g_ob  [BSHD];
__device__ __align__(16) __nv_bfloat16 g_pb  [BHSS];
__device__ __align__(16) __nv_bfloat16 g_fb  [BSF];
__device__ __align__(16) __nv_bfloat16 g_wqkv[Lc*Dc*NQKV];   // interleaved [512,6144]/layer
__device__ __align__(16) __nv_bfloat16 g_wo  [Lc*WSZ];
__device__ __align__(16) __nv_bfloat16 g_w1  [Lc*WSZ];
__device__ __align__(16) __nv_bfloat16 g_w2  [Lc*WSZ];

// ---------------- weight conversion ----------------
// QKV interleave: dst[layer][row][col], col<6144; sel = col/2048
__global__ void f2b_qkv_kernel(const float* __restrict__ Wq,
                               const float* __restrict__ Wk,
                               const float* __restrict__ Wv,
                               __nv_bfloat16* __restrict__ dst)
{
    int i = blockIdx.x * blockDim.x + threadIdx.x;       // quad index
    int total4 = Lc * Dc * NQKV / 4;
    if (i >= total4) return;
    int col = (i % (NQKV / 4)) * 4;
    int row = (i / (NQKV / 4)) % Dc;
    int layer = i / (NQKV / 4 * Dc);
    int sel = col >> 11, c = col & 2047;
    const float* src = (sel == 0 ? Wq : sel == 1 ? Wk : Wv)
                       + (size_t)layer * WSZ + (size_t)row * HDc + c;
    float4 v = *(const float4*)src;
    __nv_bfloat162 lo, hi;
    lo.x = __float2bfloat16_rn(v.x); lo.y = __float2bfloat16_rn(v.y);
    hi.x = __float2bfloat16_rn(v.z); hi.y = __float2bfloat16_rn(v.w);
    __nv_bfloat162* d2 = (__nv_bfloat162*)(dst + ((size_t)layer * Dc + row) * NQKV + col);
    d2[0] = lo; d2[1] = hi;
}

// plain convert for wo, w1, w2 in one launch
__global__ void f2b_multi_kernel(const float* __restrict__ s0, __nv_bfloat16* __restrict__ d0,
                                 const float* __restrict__ s1, __nv_bfloat16* __restrict__ d1,
                                 const float* __restrict__ s2, __nv_bfloat16* __restrict__ d2,
                                 int n4)
{
    int i = blockIdx.x * blockDim.x + threadIdx.x;
    if (i >= 3 * n4) return;
    int seg = i / n4, j = i - seg * n4;
    const float* s = (seg == 0 ? s0 : seg == 1 ? s1 : s2);
    __nv_bfloat16* d = (seg == 0 ? d0 : seg == 1 ? d1 : d2);
    float4 v = ((const float4*)s)[j];
    __nv_bfloat162 lo, hi;
    lo.x = __float2bfloat16_rn(v.x); lo.y = __float2bfloat16_rn(v.y);
    hi.x = __float2bfloat16_rn(v.z); hi.y = __float2bfloat16_rn(v.w);
    ((__nv_bfloat162*)d)[2*j]   = lo;
    ((__nv_bfloat162*)d)[2*j+1] = hi;
}

// bias concat [Lc][6144]
__global__ void bias_qkv_kernel(const float* __restrict__ bq,
                                const float* __restrict__ bk,
                                const float* __restrict__ bv,
                                float* __restrict__ dst)
{
    int i = blockIdx.x * blockDim.x + threadIdx.x;
    if (i >= Lc * NQKV) return;
    int col = i % NQKV, layer = i / NQKV;
    int sel = col >> 11, c = col & 2047;
    const float* s = (sel == 0 ? bq : sel == 1 ? bk : bv);
    dst[i] = s[layer * HDc + c];
}

// ---------------- embed ----------------
__global__ void embed_kernel(const float* __restrict__ data,
                             const float* __restrict__ seg,
                             const int*   __restrict__ view_idx,
                             float* __restrict__ x)
{
    int idx = blockIdx.x * blockDim.x + threadIdx.x;
    if (idx >= BSD) return;
    int d = idx & (Dc - 1);
    int s = (idx / Dc) & (Sc - 1);
    float angle = (float)s * exp2f(-(float)d * (1.0f / 32.0f));
    float pe = (d & 1) ? (float)cos((double)angle) : (float)sin((double)angle);
    int seg_row = view_idx[0] * Sc;
    x[idx] = data[idx] * 22.62741699796952f + pe + seg[seg_row * Dc + d];
}

// ---------------- LN helpers ----------------
__device__ __forceinline__ float2 ln_stats(float4 v, int t, float* sh)
{
    float s = v.x + v.y + v.z + v.w;
    #pragma unroll
    for (int o = 16; o; o >>= 1) s += __shfl_xor_sync(0xFFFFFFFFu, s, o);
    if ((t & 31) == 0) sh[t >> 5] = s;
    __syncthreads();
    float mean = (sh[0] + sh[1] + sh[2] + sh[3]) * (1.0f / (float)Dc);
    float dx = v.x - mean, dy = v.y - mean, dz = v.z - mean, dw = v.w - mean;
    float q = dx*dx + dy*dy + dz*dz + dw*dw;
    __syncthreads();
    #pragma unroll
    for (int o = 16; o; o >>= 1) q += __shfl_xor_sync(0xFFFFFFFFu, q, o);
    if ((t & 31) == 0) sh[t >> 5] = q;
    __syncthreads();
    float var = (sh[0] + sh[1] + sh[2] + sh[3]) * (1.0f / (float)(Dc - 1));
    float inv = 1.0f / (sqrtf(var) + 1e-6f);
    return make_float2(mean, inv);
}

__global__ void ln_bf16_kernel(const float* __restrict__ x,
                               __nv_bfloat16* __restrict__ y,
                               const float* __restrict__ alpha,
                               const float* __restrict__ beta)
{
    int row = blockIdx.x, t = threadIdx.x;
    __shared__ float sh[4];
    float4 v = ((const float4*)(x + (size_t)row * Dc))[t];
    float2 mi = ln_stats(v, t, sh);
    float4 a = ((const float4*)alpha)[t];
    float4 b = ((const float4*)beta)[t];
    __nv_bfloat162 o0, o1;
    o0.x = __float2bfloat16_rn(a.x * (v.x - mi.x) * mi.y + b.x);
    o0.y = __float2bfloat16_rn(a.y * (v.y - mi.x) * mi.y + b.y);
    o1.x = __float2bfloat16_rn(a.z * (v.z - mi.x) * mi.y + b.z);
    o1.y = __float2bfloat16_rn(a.w * (v.w - mi.x) * mi.y + b.w);
    __nv_bfloat162* yr = (__nv_bfloat162*)(y + (size_t)row * Dc);
    yr[2*t] = o0; yr[2*t+1] = o1;
}

__global__ void reduce_ln_kernel(const float* __restrict__ part,
                                 const float* __restrict__ bias,
                                 float* __restrict__ x,
                                 const float* __restrict__ alpha,
                                 const float* __restrict__ beta,
                                 __nv_bfloat16* __restrict__ ybf,
                                 float* __restrict__ yf)
{
    int row = blockIdx.x, t = threadIdx.x;
    __shared__ float sh[4];
    size_t off = (size_t)row * Dc + t * 4;
    float4 v = *(const float4*)(x + off);
    #pragma unroll
    for (int s = 0; s < 4; s++) {
        float4 p = *(const float4*)(part + (size_t)s * BSD + off);
        v.x += p.x; v.y += p.y; v.z += p.z; v.w += p.w;
    }
    float4 b4 = ((const float4*)bias)[t];
    v.x += b4.x; v.y += b4.y; v.z += b4.z; v.w += b4.w;
    *(float4*)(x + off) = v;

    float2 mi = ln_stats(v, t, sh);
    float4 a = ((const float4*)alpha)[t];
    float4 bb = ((const float4*)beta)[t];
    float y0 = a.x * (v.x - mi.x) * mi.y + bb.x;
    float y1 = a.y * (v.y - mi.x) * mi.y + bb.y;
    float y2 = a.z * (v.z - mi.x) * mi.y + bb.z;
    float y3 = a.w * (v.w - mi.x) * mi.y + bb.w;
    if (ybf) {
        __nv_bfloat162 o0, o1;
        o0.x = __float2bfloat16_rn(y0); o0.y = __float2bfloat16_rn(y1);
        o1.x = __float2bfloat16_rn(y2); o1.y = __float2bfloat16_rn(y3);
        __nv_bfloat162* yr = (__nv_bfloat162*)(ybf + (size_t)row * Dc);
        yr[2*t] = o0; yr[2*t+1] = o1;
    } else {
        *(float4*)(yf + off) = make_float4(y0, y1, y2, y3);
    }
}

// ---------------- softmax ----------------
__global__ void softmax_kernel(const float* __restrict__ s,
                               __nv_bfloat16* __restrict__ p)
{
    int gw = (blockIdx.x * blockDim.x + threadIdx.x) >> 5;
    if (gw >= Bc * Hc * Sc) return;
    int lane = threadIdx.x & 31;
    const float* r = s + (size_t)gw * Sc + lane * 8;
    float4 a = *(const float4*)r;
    float4 b = *(const float4*)(r + 4);
    float m = fmaxf(fmaxf(fmaxf(a.x, a.y), fmaxf(a.z, a.w)),
                    fmaxf(fmaxf(b.x, b.y), fmaxf(b.z, b.w)));
    #pragma unroll
    for (int o = 16; o; o >>= 1) m = fmaxf(m, __shfl_xor_sync(0xFFFFFFFFu, m, o));
    a.x = expf(a.x - m); a.y = expf(a.y - m); a.z = expf(a.z - m); a.w = expf(a.w - m);
    b.x = expf(b.x - m); b.y = expf(b.y - m); b.z = expf(b.z - m); b.w = expf(b.w - m);
    float sum = a.x + a.y + a.z + a.w + b.x + b.y + b.z + b.w;
    #pragma unroll
    for (int o = 16; o; o >>= 1) sum += __shfl_xor_sync(0xFFFFFFFFu, sum, o);
    float inv = 1.0f / sum;
    __nv_bfloat162* o2 = (__nv_bfloat162*)(p + (size_t)gw * Sc + lane * 8);
    __nv_bfloat162 h;
    h.x = __float2bfloat16_rn(a.x * inv); h.y = __float2bfloat16_rn(a.y * inv); o2[0] = h;
    h.x = __float2bfloat16_rn(a.z * inv); h.y = __float2bfloat16_rn(a.w * inv); o2[1] = h;
    h.x = __float2bfloat16_rn(b.x * inv); h.y = __float2bfloat16_rn(b.y * inv); o2[2] = h;
    h.x = __float2bfloat16_rn(b.z * inv); h.y = __float2bfloat16_rn(b.w * inv); o2[3] = h;
}

// ---------------- bf16 MMA GEMM: 128x128 tile, BK=32, 3-stage cp.async ----------
#define APADh 40
#define BPADh 136
#define ASTGh (128*APADh)
#define BSTGh_T (128*APADh)
#define BSTGh_N (32*BPADh)
#define NSTAGE 3

__device__ __forceinline__ void cpa16(void* s, const void* g) {
    uint32_t sa = (uint32_t)__cvta_generic_to_shared(s);
    asm volatile("cp.async.cg.shared.global [%0], [%1], 16;" :: "r"(sa), "l"(g) : "memory");
}
__device__ __forceinline__ void cpa_commit() {
    asm volatile("cp.async.commit_group;" ::: "memory");
}
__device__ __forceinline__ void cpa_wait2() {
    asm volatile("cp.async.wait_group 2;" ::: "memory");
}
__device__ __forceinline__ void ldsm4(uint32_t& r0, uint32_t& r1, uint32_t& r2, uint32_t& r3, uint32_t a) {
    asm volatile("ldmatrix.sync.aligned.m8n8.x4.shared.b16 {%0,%1,%2,%3}, [%4];"
                 : "=r"(r0), "=r"(r1), "=r"(r2), "=r"(r3) : "r"(a));
}
__device__ __forceinline__ void ldsm4t(uint32_t& r0, uint32_t& r1, uint32_t& r2, uint32_t& r3, uint32_t a) {
    asm volatile("ldmatrix.sync.aligned.m8n8.x4.trans.shared.b16 {%0,%1,%2,%3}, [%4];"
                 : "=r"(r0), "=r"(r1), "=r"(r2), "=r"(r3) : "r"(a));
}

template<bool TRANSB>
__global__ __launch_bounds__(256, 2)
void bgemm_kernel(const __nv_bfloat16* __restrict__ A, int lda, long long sA0, long long sA1,
                  const __nv_bfloat16* __restrict__ Bp, int ldb, long long sB0, long long sB1,
                  void* __restrict__ Cv, int ldc, long long sC0, long long sC1,
                  int zdiv, int K,
                  const float* __restrict__ bias,
                  int relu, float scale,
                  const int* __restrict__ mask, int outbf)
{
    int z = blockIdx.z;
    int zb = z / zdiv, zi = z - zb * zdiv;
    A  += zb * sA0 + zi * sA1;
    Bp += zb * sB0 + zi * sB1;
    size_t coff = (size_t)zb * sC0 + (size_t)zi * sC1;

    extern __shared__ __nv_bfloat16 sm[];
    __nv_bfloat16* As = sm;
    __nv_bfloat16* Bs = sm + NSTAGE * ASTGh;
    constexpr int BSTG = TRANSB ? BSTGh_T : BSTGh_N;

    int tid = threadIdx.x;
    int lane = tid & 31, warp = tid >> 5;
    int mBase = (warp >> 2) * 64;
    int nBase = (warp & 3) * 32;
    int lr = lane >> 2, lc = lane & 3;

    const __nv_bfloat16* Ag = A + (size_t)(blockIdx.y * 128) * lda;
    const __nv_bfloat16* Bg = TRANSB ? (Bp + (size_t)(blockIdx.x * 128) * ldb)
                                     : (Bp + blockIdx.x * 128);

    float acc[4][4][4];
    #pragma unroll
    for (int i = 0; i < 4; i++)
        #pragma unroll
        for (int j = 0; j < 4; j++)
            #pragma unroll
            for (int k = 0; k < 4; k++) acc[i][j][k] = 0.0f;

    auto load_stage = [&](int st, int kt) {
        int k0 = kt * 32;
        #pragma unroll
        for (int i = 0; i < 2; i++) {
            int ch = tid + (i << 8);
            int r = ch >> 2, c = (ch & 3) << 3;
            cpa16(&As[st * ASTGh + r * APADh + c], Ag + (size_t)r * lda + k0 + c);
        }
        if (TRANSB) {
            #pragma unroll
            for (int i = 0; i < 2; i++) {
                int ch = tid + (i << 8);
                int r = ch >> 2, c = (ch & 3) << 3;
                cpa16(&Bs[st * BSTG + r * APADh + c], Bg + (size_t)r * ldb + k0 + c);
            }
        } else {
            #pragma unroll
            for (int i = 0; i < 2; i++) {
                int ch = tid + (i << 8);
                int r = ch >> 4, c = (ch & 15) << 3;
                cpa16(&Bs[st * BSTG + r * BPADh + c], Bg + (size_t)(k0 + r) * ldb + c);
            }
        }
    };

    uint32_t aBase = (uint32_t)__cvta_generic_to_shared(As);
    uint32_t bBase = (uint32_t)__cvta_generic_to_shared(Bs);
    int aRow[4];
    #pragma unroll
    for (int mt = 0; mt < 4; mt++)
        aRow[mt] = (mBase + mt * 16 + (lane & 15)) * APADh + ((lane >> 4) << 3);
    int bRow[2];
    #pragma unroll
    for (int p = 0; p < 2; p++) {
        if (TRANSB)
            bRow[p] = (nBase + p * 16 + (lane & 7) + (((lane >> 4) & 1) << 3)) * APADh
                      + (((lane >> 3) & 1) << 3);
        else
            bRow[p] = ((lane & 7) + (((lane >> 3) & 1) << 3)) * BPADh
                      + nBase + p * 16 + (((lane >> 4) & 1) << 3);
    }

    int kTiles = K >> 5;
    load_stage(0, 0);
    cpa_commit();
    if (kTiles > 1) load_stage(1, 1);
    cpa_commit();
    if (kTiles > 2) load_stage(2, 2);
    cpa_commit();

    int st = 0;
    for (int kt = 0; kt < kTiles; kt++) {
        cpa_wait2();
        __syncthreads();
        uint32_t aS = aBase + st * (ASTGh * 2);
        uint32_t bS = bBase + st * (BSTG * 2);

        #pragma unroll
        for (int kk = 0; kk < 32; kk += 16) {
            uint32_t af[4][4], bf[4][2];
            #pragma unroll
            for (int mt = 0; mt < 4; mt++)
                ldsm4(af[mt][0], af[mt][1], af[mt][2], af[mt][3],
                      aS + 2 * (aRow[mt] + kk));
            #pragma unroll
            for (int p = 0; p < 2; p++) {
                if (TRANSB)
                    ldsm4(bf[2*p][0], bf[2*p][1], bf[2*p+1][0], bf[2*p+1][1],
                          bS + 2 * (bRow[p] + kk));
                else
                    ldsm4t(bf[2*p][0], bf[2*p][1], bf[2*p+1][0], bf[2*p+1][1],
                           bS + 2 * (bRow[p] + kk * BPADh));
            }
            #pragma unroll
            for (int mt = 0; mt < 4; mt++)
                #pragma unroll
                for (int nt = 0; nt < 4; nt++) {
                    asm volatile(
                        "mma.sync.aligned.m16n8k16.row.col.f32.bf16.bf16.f32 "
                        "{%0,%1,%2,%3}, {%4,%5,%6,%7}, {%8,%9}, {%0,%1,%2,%3};"
                        : "+f"(acc[mt][nt][0]), "+f"(acc[mt][nt][1]),
                          "+f"(acc[mt][nt][2]), "+f"(acc[mt][nt][3])
                        : "r"(af[mt][0]), "r"(af[mt][1]), "r"(af[mt][2]), "r"(af[mt][3]),
                          "r"(bf[nt][0]), "r"(bf[nt][1]));
                }
        }
        __syncthreads();
        if (kt + 3 < kTiles) load_stage(st, kt + 3);
        cpa_commit();
        st = (st == NSTAGE - 1) ? 0 : st + 1;
    }

    // ---------------- epilogue ----------------
    float* Cf = (float*)Cv + coff;
    __nv_bfloat16* Cb = (__nv_bfloat16*)Cv + coff;
    #pragma unroll
    for (int mt = 0; mt < 4; mt++) {
        #pragma unroll
        for (int nt = 0; nt < 4; nt++) {
            int row0 = blockIdx.y * 128 + mBase + mt * 16 + lr;
            int col  = blockIdx.x * 128 + nBase + nt * 8 + lc * 2;
            float b0 = bias ? bias[col]     : 0.0f;
            float b1 = bias ? bias[col + 1] : 0.0f;
            int m0 = mask ? mask[zb * Sc + col]     : 0;
            int m1 = mask ? mask[zb * Sc + col + 1] : 0;
            #pragma unroll
            for (int h = 0; h < 2; h++) {
                int row = row0 + h * 8;
                float c0 = acc[mt][nt][h * 2 + 0] + b0;
                float c1 = acc[mt][nt][h * 2 + 1] + b1;
                c0 *= scale; c1 *= scale;
                if (mask) { if (m0) c0 = -1e9f; if (m1) c1 = -1e9f; }
                if (relu) { c0 = fmaxf(c0, 0.0f); c1 = fmaxf(c1, 0.0f); }
                size_t off = (size_t)row * ldc + col;
                if (outbf) {
                    __nv_bfloat162 h2;
                    h2.x = __float2bfloat16_rn(c0);
                    h2.y = __float2bfloat16_rn(c1);
                    *(__nv_bfloat162*)(Cb + off) = h2;
                } else {
                    *(float2*)(Cf + off) = make_float2(c0, c1);
                }
            }
        }
    }
}

#define SMEM_BT ((NSTAGE*ASTGh + NSTAGE*BSTGh_T) * 2)
#define SMEM_BN ((NSTAGE*ASTGh + NSTAGE*BSTGh_N) * 2)

static void bgemm(const __nv_bfloat16* A, int lda, long long sA0, long long sA1,
                  const __nv_bfloat16* B, int ldb, long long sB0, long long sB1,
                  void* C, int ldc, long long sC0, long long sC1,
                  int zdiv, int M, int N, int K, int nz,
                  const float* bias, int relu, float scale,
                  const int* mask, int outbf, bool transb)
{
    dim3 grid(N / 128, M / 128, nz), block(256);
    static bool attrSet = false;
    if (!attrSet) {
        cudaFuncSetAttribute(bgemm_kernel<true>,
                             cudaFuncAttributeMaxDynamicSharedMemorySize, SMEM_BT);
        cudaFuncSetAttribute(bgemm_kernel<false>,
                             cudaFuncAttributeMaxDynamicSharedMemorySize, SMEM_BN);
        attrSet = true;
    }
    if (transb)
        bgemm_kernel<true><<<grid, block, SMEM_BT>>>(A, lda, sA0, sA1, B, ldb, sB0, sB1,
                                                     C, ldc, sC0, sC1, zdiv, K,
                                                     bias, relu, scale, mask, outbf);
    else
        bgemm_kernel<false><<<grid, block, SMEM_BN>>>(A, lda, sA0, sA1, B, ldb, sB0, sB1,
                                                      C, ldc, sC0, sC1, zdiv, K,
                                                      bias, relu, scale, mask, outbf);
}

extern "C" void kernel_launch(void* const* d_in, const int* in_sizes, int n_in,
                              void* d_out, int out_size)
{
    const float* data    = (const float*)d_in[0];
    const int*   attn_m  = (const int*)  d_in[1];
    const int*   view_ix = (const int*)  d_in[2];
    const float* seg     = (const float*)d_in[3];
    const float* Wq = (const float*)d_in[4];
    const float* bq = (const float*)d_in[5];
    const float* Wk = (const float*)d_in[6];
    const float* bk = (const float*)d_in[7];
    const float* Wv = (const float*)d_in[8];
    const float* bv = (const float*)d_in[9];
    const float* Wo = (const float*)d_in[10];
    const float* bo = (const float*)d_in[11];
    const float* W1 = (const float*)d_in[12];
    const float* b1 = (const float*)d_in[13];
    const float* W2 = (const float*)d_in[14];
    const float* b2 = (const float*)d_in[15];
    const float* alpha1 = (const float*)d_in[16];
    const float* bias1  = (const float*)d_in[17];
    const float* alpha2 = (const float*)d_in[18];
    const float* bias2  = (const float*)d_in[19];
    const float* alphaf = (const float*)d_in[20];
    const float* biasf  = (const float*)d_in[21];
    float* out = (float*)d_out;

    static float *px = nullptr, *ps, *ppart, *pbqkv;
    static __nv_bfloat16 *px2b, *pqkv, *pob, *ppb, *pfb;
    static __nv_bfloat16 *wqkv, *wo, *w1, *w2;
    if (!px) {
        cudaGetSymbolAddress((void**)&px,    g_x);
        cudaGetSymbolAddress((void**)&ps,    g_s);
        cudaGetSymbolAddress((void**)&ppart, g_part);
        cudaGetSymbolAddress((void**)&pbqkv, g_bqkv);
        cudaGetSymbolAddress((void**)&px2b,  g_x2b);
        cudaGetSymbolAddress((void**)&pqkv,  g_qkvb);
        cudaGetSymbolAddress((void**)&pob,   g_ob);
        cudaGetSymbolAddress((void**)&ppb,   g_pb);
        cudaGetSymbolAddress((void**)&pfb,   g_fb);
        cudaGetSymbolAddress((void**)&wqkv,  g_wqkv);
        cudaGetSymbolAddress((void**)&wo,    g_wo);
        cudaGetSymbolAddress((void**)&w1,    g_w1);
        cudaGetSymbolAddress((void**)&w2,    g_w2);
    }

    // weight conversion
    {
        int t4 = Lc * Dc * NQKV / 4;
        f2b_qkv_kernel<<<(t4 + 255) / 256, 256>>>(Wq, Wk, Wv, wqkv);
        int n4 = Lc * WSZ / 4;
        f2b_multi_kernel<<<(3 * n4 + 255) / 256, 256>>>(Wo, wo, W1, w1, W2, w2, n4);
        bias_qkv_kernel<<<(Lc * NQKV + 255) / 256, 256>>>(bq, bk, bv, pbqkv);
    }

    embed_kernel<<<(BSD + 255) / 256, 256>>>(data, seg, view_ix, px);
    ln_bf16_kernel<<<Bc * Sc, 128>>>(px, px2b, alpha1, bias1);

    const float iscale = 0.0625f;

    for (int i = 0; i < Lc; i++) {
        // fused QKV: [2048,512]@[512,6144] -> bf16 [2048,6144]
        bgemm(px2b, Dc, 0, 0, wqkv + (long long)i * Dc * NQKV, NQKV, 0, 0,
              pqkv, NQKV, 0, 0, 1, Bc * Sc, NQKV, Dc, 1,
              pbqkv + i * NQKV, 0, 1.0f, nullptr, 1, false);

        // scores = Q @ K^T * 1/16, masked -> fp32
        bgemm(pqkv, NQKV, (long long)Sc * NQKV, DKc,
              pqkv + HDc, NQKV, (long long)Sc * NQKV, DKc,
              ps, Sc, (long long)Hc * Sc * Sc, (long long)Sc * Sc,
              Hc, Sc, Sc, DKc, Bc * Hc,
              nullptr, 0, iscale, attn_m, 0, true);

        softmax_kernel<<<(Bc * Hc * Sc) / 8, 256>>>(ps, ppb);

        // o = P @ V -> bf16 in [B,S,H*DK]
        bgemm(ppb, Sc, (long long)Hc * Sc * Sc, (long long)Sc * Sc,
              pqkv + 2 * HDc, NQKV, (long long)Sc * NQKV, DKc,
              pob, HDc, (long long)Sc * HDc, DKc,
              Hc, Sc, DKc, Sc, Bc * Hc,
              nullptr, 0, 1.0f, nullptr, 1, false);

        // Wo: split-K=4 partials
        bgemm(pob, HDc, 0, DKc * 2,
              wo + (long long)i * WSZ, Dc, 0, (long long)512 * Dc,
              ppart, Dc, 0, (long long)BSD,
              4, Bc * Sc, Dc, HDc / 4, 4,
              nullptr, 0, 1.0f, nullptr, 0, false);
        reduce_ln_kernel<<<Bc * Sc, 128>>>(ppart, bo + i * Dc, px,
                                           alpha2 + i * Dc, bias2 + i * Dc,
                                           px2b, nullptr);

        // ff = relu(x2 @ W1 + b1) -> bf16
        bgemm(px2b, Dc, 0, 0, w1 + (long long)i * WSZ, DFFc, 0, 0,
              pfb, DFFc, 0, 0, 1, Bc * Sc, DFFc, Dc, 1,
              b1 + i * DFFc, 1, 1.0f, nullptr, 1, false);

        // W2: split-K=4 partials
        bgemm(pfb, DFFc, 0, DKc * 2,
              w2 + (long long)i * WSZ, Dc, 0, (long long)512 * Dc,
              ppart, Dc, 0, (long long)BSD,
              4, Bc * Sc, Dc, DFFc / 4, 4,
              nullptr, 0, 1.0f, nullptr, 0, false);

        if (i < Lc - 1)
            reduce_ln_kernel<<<Bc * Sc, 128>>>(ppart, b2 + i * Dc, px,
                                               alpha1 + (i + 1) * Dc, bias1 + (i + 1) * Dc,
                                               px2b, nullptr);
        else
            reduce_ln_kernel<<<Bc * Sc, 128>>>(ppart, b2 + i * Dc, px,
                                               alphaf, biasf,
                                               nullptr, out);
    }
}

// round 6
// speedup vs baseline: 9.1834x; 1.0626x over previous
#include <cuda_runtime.h>
#include <cuda_bf16.h>
#include <math.h>
#include <stdint.h>

// ---------------- constants ----------------
#define Bc   8
#define Sc   256
#define Dc   512
#define Hc   8
#define DKc  256
#define HDc  2048
#define DFFc 2048
#define Lc   4
#define NQKV 6144

#define BSD  (Bc*Sc*Dc)
#define BSHD (Bc*Sc*HDc)
#define BSF  (Bc*Sc*DFFc)
#define WSZ  (Dc*HDc)

// ---------------- scratch ----------------
__device__ __align__(16) float g_x   [BSD];
__device__ __align__(16) float g_part[4*BSD];
__device__ __align__(16) float g_bqkv[Lc*NQKV];
__device__ __align__(16) __nv_bfloat16 g_x2b [BSD];
__device__ __align__(16) __nv_bfloat16 g_qkvb[Bc*Sc*NQKV];
__device__ __align__(16) __nv_bfloat16 g_ob  [BSHD];
__device__ __align__(16) __nv_bfloat16 g_fb  [BSF];
__device__ __align__(16) __nv_bfloat16 g_wqkv[Lc*Dc*NQKV];
__device__ __align__(16) __nv_bfloat16 g_wo  [Lc*WSZ];
__device__ __align__(16) __nv_bfloat16 g_w1  [Lc*WSZ];
__device__ __align__(16) __nv_bfloat16 g_w2  [Lc*WSZ];

// ---------------- async copy helpers ----------------
__device__ __forceinline__ void cpa16(void* s, const void* g) {
    uint32_t sa = (uint32_t)__cvta_generic_to_shared(s);
    asm volatile("cp.async.cg.shared.global [%0], [%1], 16;" :: "r"(sa), "l"(g) : "memory");
}
__device__ __forceinline__ void cpa_commit() {
    asm volatile("cp.async.commit_group;" ::: "memory");
}
__device__ __forceinline__ void cpa_wait0() {
    asm volatile("cp.async.wait_group 0;" ::: "memory");
}
__device__ __forceinline__ void cpa_wait2() {
    asm volatile("cp.async.wait_group 2;" ::: "memory");
}
__device__ __forceinline__ void ldsm4(uint32_t& r0, uint32_t& r1, uint32_t& r2, uint32_t& r3, uint32_t a) {
    asm volatile("ldmatrix.sync.aligned.m8n8.x4.shared.b16 {%0,%1,%2,%3}, [%4];"
                 : "=r"(r0), "=r"(r1), "=r"(r2), "=r"(r3) : "r"(a));
}
__device__ __forceinline__ void ldsm4t(uint32_t& r0, uint32_t& r1, uint32_t& r2, uint32_t& r3, uint32_t a) {
    asm volatile("ldmatrix.sync.aligned.m8n8.x4.trans.shared.b16 {%0,%1,%2,%3}, [%4];"
                 : "=r"(r0), "=r"(r1), "=r"(r2), "=r"(r3) : "r"(a));
}
#define MMA_BF16(acc, a0,a1,a2,a3, b0,b1) \
    asm volatile("mma.sync.aligned.m16n8k16.row.col.f32.bf16.bf16.f32 " \
                 "{%0,%1,%2,%3}, {%4,%5,%6,%7}, {%8,%9}, {%0,%1,%2,%3};" \
                 : "+f"(acc[0]), "+f"(acc[1]), "+f"(acc[2]), "+f"(acc[3]) \
                 : "r"(a0), "r"(a1), "r"(a2), "r"(a3), "r"(b0), "r"(b1))

// ---------------- weight conversion ----------------
__global__ void f2b_qkv_kernel(const float* __restrict__ Wq,
                               const float* __restrict__ Wk,
                               const float* __restrict__ Wv,
                               __nv_bfloat16* __restrict__ dst)
{
    int i = blockIdx.x * blockDim.x + threadIdx.x;
    int total4 = Lc * Dc * NQKV / 4;
    if (i >= total4) return;
    int col = (i % (NQKV / 4)) * 4;
    int row = (i / (NQKV / 4)) % Dc;
    int layer = i / (NQKV / 4 * Dc);
    int sel = col >> 11, c = col & 2047;
    const float* src = (sel == 0 ? Wq : sel == 1 ? Wk : Wv)
                       + (size_t)layer * WSZ + (size_t)row * HDc + c;
    float4 v = *(const float4*)src;
    __nv_bfloat162 lo, hi;
    lo.x = __float2bfloat16_rn(v.x); lo.y = __float2bfloat16_rn(v.y);
    hi.x = __float2bfloat16_rn(v.z); hi.y = __float2bfloat16_rn(v.w);
    __nv_bfloat162* d2 = (__nv_bfloat162*)(dst + ((size_t)layer * Dc + row) * NQKV + col);
    d2[0] = lo; d2[1] = hi;
}

__global__ void f2b_multi_kernel(const float* __restrict__ s0, __nv_bfloat16* __restrict__ d0,
                                 const float* __restrict__ s1, __nv_bfloat16* __restrict__ d1,
                                 const float* __restrict__ s2, __nv_bfloat16* __restrict__ d2,
                                 int n4)
{
    int i = blockIdx.x * blockDim.x + threadIdx.x;
    if (i >= 3 * n4) return;
    int seg = i / n4, j = i - seg * n4;
    const float* s = (seg == 0 ? s0 : seg == 1 ? s1 : s2);
    __nv_bfloat16* d = (seg == 0 ? d0 : seg == 1 ? d1 : d2);
    float4 v = ((const float4*)s)[j];
    __nv_bfloat162 lo, hi;
    lo.x = __float2bfloat16_rn(v.x); lo.y = __float2bfloat16_rn(v.y);
    hi.x = __float2bfloat16_rn(v.z); hi.y = __float2bfloat16_rn(v.w);
    ((__nv_bfloat162*)d)[2*j]   = lo;
    ((__nv_bfloat162*)d)[2*j+1] = hi;
}

__global__ void bias_qkv_kernel(const float* __restrict__ bq,
                                const float* __restrict__ bk,
                                const float* __restrict__ bv,
                                float* __restrict__ dst)
{
    int i = blockIdx.x * blockDim.x + threadIdx.x;
    if (i >= Lc * NQKV) return;
    int col = i % NQKV, layer = i / NQKV;
    int sel = col >> 11, c = col & 2047;
    const float* s = (sel == 0 ? bq : sel == 1 ? bk : bv);
    dst[i] = s[layer * HDc + c];
}

// ---------------- embed ----------------
__global__ void embed_kernel(const float* __restrict__ data,
                             const float* __restrict__ seg,
                             const int*   __restrict__ view_idx,
                             float* __restrict__ x)
{
    int idx = blockIdx.x * blockDim.x + threadIdx.x;
    if (idx >= BSD) return;
    int d = idx & (Dc - 1);
    int s = (idx / Dc) & (Sc - 1);
    float angle = (float)s * exp2f(-(float)d * (1.0f / 32.0f));
    float pe = (d & 1) ? cosf(angle) : sinf(angle);
    int seg_row = view_idx[0] * Sc;
    x[idx] = data[idx] * 22.62741699796952f + pe + seg[seg_row * Dc + d];
}

// ---------------- LN helpers ----------------
__device__ __forceinline__ float2 ln_stats(float4 v, int t, float* sh)
{
    float s = v.x + v.y + v.z + v.w;
    #pragma unroll
    for (int o = 16; o; o >>= 1) s += __shfl_xor_sync(0xFFFFFFFFu, s, o);
    if ((t & 31) == 0) sh[t >> 5] = s;
    __syncthreads();
    float mean = (sh[0] + sh[1] + sh[2] + sh[3]) * (1.0f / (float)Dc);
    float dx = v.x - mean, dy = v.y - mean, dz = v.z - mean, dw = v.w - mean;
    float q = dx*dx + dy*dy + dz*dz + dw*dw;
    __syncthreads();
    #pragma unroll
    for (int o = 16; o; o >>= 1) q += __shfl_xor_sync(0xFFFFFFFFu, q, o);
    if ((t & 31) == 0) sh[t >> 5] = q;
    __syncthreads();
    float var = (sh[0] + sh[1] + sh[2] + sh[3]) * (1.0f / (float)(Dc - 1));
    float inv = 1.0f / (sqrtf(var) + 1e-6f);
    return make_float2(mean, inv);
}

__global__ void ln_bf16_kernel(const float* __restrict__ x,
                               __nv_bfloat16* __restrict__ y,
                               const float* __restrict__ alpha,
                               const float* __restrict__ beta)
{
    int row = blockIdx.x, t = threadIdx.x;
    __shared__ float sh[4];
    float4 v = ((const float4*)(x + (size_t)row * Dc))[t];
    float2 mi = ln_stats(v, t, sh);
    float4 a = ((const float4*)alpha)[t];
    float4 b = ((const float4*)beta)[t];
    __nv_bfloat162 o0, o1;
    o0.x = __float2bfloat16_rn(a.x * (v.x - mi.x) * mi.y + b.x);
    o0.y = __float2bfloat16_rn(a.y * (v.y - mi.x) * mi.y + b.y);
    o1.x = __float2bfloat16_rn(a.z * (v.z - mi.x) * mi.y + b.z);
    o1.y = __float2bfloat16_rn(a.w * (v.w - mi.x) * mi.y + b.w);
    __nv_bfloat162* yr = (__nv_bfloat162*)(y + (size_t)row * Dc);
    yr[2*t] = o0; yr[2*t+1] = o1;
}

__global__ void reduce_ln_kernel(const float* __restrict__ part,
                                 const float* __restrict__ bias,
                                 float* __restrict__ x,
                                 const float* __restrict__ alpha,
                                 const float* __restrict__ beta,
                                 __nv_bfloat16* __restrict__ ybf,
                                 float* __restrict__ yf)
{
    int row = blockIdx.x, t = threadIdx.x;
    __shared__ float sh[4];
    size_t off = (size_t)row * Dc + t * 4;
    float4 v = *(const float4*)(x + off);
    #pragma unroll
    for (int s = 0; s < 4; s++) {
        float4 p = *(const float4*)(part + (size_t)s * BSD + off);
        v.x += p.x; v.y += p.y; v.z += p.z; v.w += p.w;
    }
    float4 b4 = ((const float4*)bias)[t];
    v.x += b4.x; v.y += b4.y; v.z += b4.z; v.w += b4.w;
    *(float4*)(x + off) = v;

    float2 mi = ln_stats(v, t, sh);
    float4 a = ((const float4*)alpha)[t];
    float4 bb = ((const float4*)beta)[t];
    float y0 = a.x * (v.x - mi.x) * mi.y + bb.x;
    float y1 = a.y * (v.y - mi.x) * mi.y + bb.y;
    float y2 = a.z * (v.z - mi.x) * mi.y + bb.z;
    float y3 = a.w * (v.w - mi.x) * mi.y + bb.w;
    if (ybf) {
        __nv_bfloat162 o0, o1;
        o0.x = __float2bfloat16_rn(y0); o0.y = __float2bfloat16_rn(y1);
        o1.x = __float2bfloat16_rn(y2); o1.y = __float2bfloat16_rn(y3);
        __nv_bfloat162* yr = (__nv_bfloat162*)(ybf + (size_t)row * Dc);
        yr[2*t] = o0; yr[2*t+1] = o1;
    } else {
        *(float4*)(yf + off) = make_float4(y0, y1, y2, y3);
    }
}

// ---------------- fused attention ----------------
// grid (2 qtiles, 64 bh), 512 threads.
// phase1: S = Q(128x256) @ K^T -> softmax in-register -> P bf16 in smem
// phase2: O = P @ V(256x256) -> bf16 out
#define PQA 264   // halves pitch, Q/P tile (128 rows)
#define PKA 264   // halves pitch, K/V tile (256 rows)
#define ATT_SMEM ((128*PQA + 256*PKA) * 2 + 512*4 + 256*4)

__global__ __launch_bounds__(512, 1)
void attn_kernel(const __nv_bfloat16* __restrict__ qkv,
                 const int* __restrict__ attn_m,
                 __nv_bfloat16* __restrict__ out)
{
    extern __shared__ __nv_bfloat16 smh[];
    __nv_bfloat16* sQ = smh;                      // 128 x PQA (later P)
    __nv_bfloat16* sK = smh + 128 * PQA;          // 256 x PKA (later V)
    float* red  = (float*)(smh + 128 * PQA + 256 * PKA);   // [4][128]
    int*  smask = (int*)(red + 512);                        // [256]

    int qt = blockIdx.x, bh = blockIdx.y;
    int b = bh >> 3, h = bh & 7;
    int tid = threadIdx.x, lane = tid & 31, warp = tid >> 5;
    int mw = warp >> 2, nw = warp & 3;
    int lr = lane >> 2, lc = lane & 3;

    const __nv_bfloat16* Qg = qkv + (size_t)(b * Sc + qt * 128) * NQKV + h * DKc;
    const __nv_bfloat16* Kg = qkv + (size_t)(b * Sc) * NQKV + HDc + h * DKc;
    const __nv_bfloat16* Vg = qkv + (size_t)(b * Sc) * NQKV + 2 * HDc + h * DKc;

    // load Q (128x256) + K (256x256) + mask
    #pragma unroll
    for (int i = 0; i < 8; i++) {
        int ch = tid + i * 512;
        int r = ch >> 5, c = (ch & 31) << 3;
        cpa16(&sQ[r * PQA + c], Qg + (size_t)r * NQKV + c);
    }
    #pragma unroll
    for (int i = 0; i < 16; i++) {
        int ch = tid + i * 512;
        int r = ch >> 5, c = (ch & 31) << 3;
        cpa16(&sK[r * PKA + c], Kg + (size_t)r * NQKV + c);
    }
    if (tid < 256) smask[tid] = attn_m[b * Sc + tid];
    cpa_commit();
    cpa_wait0();
    __syncthreads();

    uint32_t qBase = (uint32_t)__cvta_generic_to_shared(sQ);
    uint32_t kBase = (uint32_t)__cvta_generic_to_shared(sK);

    int aOff[2];
    #pragma unroll
    for (int mi = 0; mi < 2; mi++)
        aOff[mi] = (mw * 32 + mi * 16 + (lane & 15)) * PQA + ((lane >> 4) << 3);
    int bOff1[4];
    #pragma unroll
    for (int p = 0; p < 4; p++)
        bOff1[p] = (nw * 64 + p * 16 + (lane & 7) + (((lane >> 4) & 1) << 3)) * PKA
                   + (((lane >> 3) & 1) << 3);

    float acc[2][8][4];
    #pragma unroll
    for (int mi = 0; mi < 2; mi++)
        #pragma unroll
        for (int ni = 0; ni < 8; ni++)
            #pragma unroll
            for (int k = 0; k < 4; k++) acc[mi][ni][k] = 0.0f;

    // phase 1: S = Q @ K^T
    #pragma unroll
    for (int kk = 0; kk < 256; kk += 16) {
        uint32_t af[2][4], bf[8][2];
        #pragma unroll
        for (int mi = 0; mi < 2; mi++)
            ldsm4(af[mi][0], af[mi][1], af[mi][2], af[mi][3], qBase + 2 * (aOff[mi] + kk));
        #pragma unroll
        for (int p = 0; p < 4; p++)
            ldsm4(bf[2*p][0], bf[2*p][1], bf[2*p+1][0], bf[2*p+1][1],
                  kBase + 2 * (bOff1[p] + kk));
        #pragma unroll
        for (int mi = 0; mi < 2; mi++)
            #pragma unroll
            for (int ni = 0; ni < 8; ni++)
                MMA_BF16(acc[mi][ni], af[mi][0], af[mi][1], af[mi][2], af[mi][3],
                         bf[ni][0], bf[ni][1]);
    }
    __syncthreads();   // all reads of sQ/sK done

    // overlap: start V load into sK
    #pragma unroll
    for (int i = 0; i < 16; i++) {
        int ch = tid + i * 512;
        int r = ch >> 5, c = (ch & 31) << 3;
        cpa16(&sK[r * PKA + c], Vg + (size_t)r * NQKV + c);
    }
    cpa_commit();

    // scale + mask
    #pragma unroll
    for (int ni = 0; ni < 8; ni++) {
        int col = nw * 64 + ni * 8 + lc * 2;
        int mk0 = smask[col], mk1 = smask[col + 1];
        #pragma unroll
        for (int mi = 0; mi < 2; mi++) {
            #pragma unroll
            for (int hh = 0; hh < 2; hh++) {
                float v0 = acc[mi][ni][hh * 2]     * 0.0625f;
                float v1 = acc[mi][ni][hh * 2 + 1] * 0.0625f;
                acc[mi][ni][hh * 2]     = mk0 ? -1e9f : v0;
                acc[mi][ni][hh * 2 + 1] = mk1 ? -1e9f : v1;
            }
        }
    }

    // row max: thread-local -> quad shfl -> cross-warp via smem
    float mx[2][2];
    #pragma unroll
    for (int mi = 0; mi < 2; mi++)
        #pragma unroll
        for (int hh = 0; hh < 2; hh++) {
            float m = -3e38f;
            #pragma unroll
            for (int ni = 0; ni < 8; ni++)
                m = fmaxf(m, fmaxf(acc[mi][ni][hh * 2], acc[mi][ni][hh * 2 + 1]));
            m = fmaxf(m, __shfl_xor_sync(0xFFFFFFFFu, m, 1));
            m = fmaxf(m, __shfl_xor_sync(0xFFFFFFFFu, m, 2));
            mx[mi][hh] = m;
        }
    if (lc == 0) {
        #pragma unroll
        for (int mi = 0; mi < 2; mi++)
            #pragma unroll
            for (int hh = 0; hh < 2; hh++)
                red[nw * 128 + mw * 32 + mi * 16 + hh * 8 + lr] = mx[mi][hh];
    }
    __syncthreads();
    #pragma unroll
    for (int mi = 0; mi < 2; mi++)
        #pragma unroll
        for (int hh = 0; hh < 2; hh++) {
            int row = mw * 32 + mi * 16 + hh * 8 + lr;
            mx[mi][hh] = fmaxf(fmaxf(red[row], red[128 + row]),
                               fmaxf(red[256 + row], red[384 + row]));
        }
    __syncthreads();   // before reusing red for sums

    // exp + row sum
    float sums[2][2];
    #pragma unroll
    for (int mi = 0; mi < 2; mi++)
        #pragma unroll
        for (int hh = 0; hh < 2; hh++) {
            float s = 0.0f;
            #pragma unroll
            for (int ni = 0; ni < 8; ni++) {
                float e0 = expf(acc[mi][ni][hh * 2]     - mx[mi][hh]);
                float e1 = expf(acc[mi][ni][hh * 2 + 1] - mx[mi][hh]);
                acc[mi][ni][hh * 2]     = e0;
                acc[mi][ni][hh * 2 + 1] = e1;
                s += e0 + e1;
            }
            s += __shfl_xor_sync(0xFFFFFFFFu, s, 1);
            s += __shfl_xor_sync(0xFFFFFFFFu, s, 2);
            sums[mi][hh] = s;
        }
    if (lc == 0) {
        #pragma unroll
        for (int mi = 0; mi < 2; mi++)
            #pragma unroll
            for (int hh = 0; hh < 2; hh++)
                red[nw * 128 + mw * 32 + mi * 16 + hh * 8 + lr] = sums[mi][hh];
    }
    __syncthreads();
    #pragma unroll
    for (int mi = 0; mi < 2; mi++)
        #pragma unroll
        for (int hh = 0; hh < 2; hh++) {
            int row = mw * 32 + mi * 16 + hh * 8 + lr;
            float tot = red[row] + red[128 + row] + red[256 + row] + red[384 + row];
            sums[mi][hh] = 1.0f / tot;
        }

    // write P (bf16) into sQ
    #pragma unroll
    for (int mi = 0; mi < 2; mi++)
        #pragma unroll
        for (int hh = 0; hh < 2; hh++) {
            int row = mw * 32 + mi * 16 + hh * 8 + lr;
            float inv = sums[mi][hh];
            #pragma unroll
            for (int ni = 0; ni < 8; ni++) {
                int col = nw * 64 + ni * 8 + lc * 2;
                __nv_bfloat162 pr;
                pr.x = __float2bfloat16_rn(acc[mi][ni][hh * 2]     * inv);
                pr.y = __float2bfloat16_rn(acc[mi][ni][hh * 2 + 1] * inv);
                *(__nv_bfloat162*)(sQ + row * PQA + col) = pr;
            }
        }
    cpa_wait0();
    __syncthreads();

    // phase 2: O = P @ V
    int bOff2[4];
    #pragma unroll
    for (int p = 0; p < 4; p++)
        bOff2[p] = ((lane & 7) + (((lane >> 3) & 1) << 3)) * PKA
                   + nw * 64 + p * 16 + (((lane >> 4) & 1) << 3);

    #pragma unroll
    for (int mi = 0; mi < 2; mi++)
        #pragma unroll
        for (int ni = 0; ni < 8; ni++)
            #pragma unroll
            for (int k = 0; k < 4; k++) acc[mi][ni][k] = 0.0f;

    #pragma unroll
    for (int kk = 0; kk < 256; kk += 16) {
        uint32_t af[2][4], bf[8][2];
        #pragma unroll
        for (int mi = 0; mi < 2; mi++)
            ldsm4(af[mi][0], af[mi][1], af[mi][2], af[mi][3], qBase + 2 * (aOff[mi] + kk));
        #pragma unroll
        for (int p = 0; p < 4; p++)
            ldsm4t(bf[2*p][0], bf[2*p][1], bf[2*p+1][0], bf[2*p+1][1],
                   kBase + 2 * (bOff2[p] + kk * PKA));
        #pragma unroll
        for (int mi = 0; mi < 2; mi++)
            #pragma unroll
            for (int ni = 0; ni < 8; ni++)
                MMA_BF16(acc[mi][ni], af[mi][0], af[mi][1], af[mi][2], af[mi][3],
                         bf[ni][0], bf[ni][1]);
    }

    // epilogue: O -> g_ob [B*S, HD]
    #pragma unroll
    for (int mi = 0; mi < 2; mi++)
        #pragma unroll
        for (int ni = 0; ni < 8; ni++) {
            int col = h * DKc + nw * 64 + ni * 8 + lc * 2;
            #pragma unroll
            for (int hh = 0; hh < 2; hh++) {
                int grow = b * Sc + qt * 128 + mw * 32 + mi * 16 + hh * 8 + lr;
                __nv_bfloat162 o2;
                o2.x = __float2bfloat16_rn(acc[mi][ni][hh * 2]);
                o2.y = __float2bfloat16_rn(acc[mi][ni][hh * 2 + 1]);
                *(__nv_bfloat162*)(out + (size_t)grow * HDc + col) = o2;
            }
        }
}

// ---------------- bf16 MMA GEMM (3-stage cp.async) ----------------
#define APADh 40
#define BPADh 136
#define ASTGh (128*APADh)
#define BSTGh (32*BPADh)
#define NSTAGE 3

__global__ __launch_bounds__(256, 2)
void bgemm_kernel(const __nv_bfloat16* __restrict__ A, int lda, long long sA0, long long sA1,
                  const __nv_bfloat16* __restrict__ Bp, int ldb, long long sB0, long long sB1,
                  void* __restrict__ Cv, int ldc, long long sC0, long long sC1,
                  int zdiv, int K,
                  const float* __restrict__ bias,
                  int relu, float scale, int outbf)
{
    int z = blockIdx.z;
    int zb = z / zdiv, zi = z - zb * zdiv;
    A  += zb * sA0 + zi * sA1;
    Bp += zb * sB0 + zi * sB1;
    size_t coff = (size_t)zb * sC0 + (size_t)zi * sC1;

    extern __shared__ __nv_bfloat16 sm[];
    __nv_bfloat16* As = sm;
    __nv_bfloat16* Bs = sm + NSTAGE * ASTGh;

    int tid = threadIdx.x;
    int lane = tid & 31, warp = tid >> 5;
    int mBase = (warp >> 2) * 64;
    int nBase = (warp & 3) * 32;
    int lr = lane >> 2, lc = lane & 3;

    const __nv_bfloat16* Ag = A + (size_t)(blockIdx.y * 128) * lda;
    const __nv_bfloat16* Bg = Bp + blockIdx.x * 128;

    float acc[4][4][4];
    #pragma unroll
    for (int i = 0; i < 4; i++)
        #pragma unroll
        for (int j = 0; j < 4; j++)
            #pragma unroll
            for (int k = 0; k < 4; k++) acc[i][j][k] = 0.0f;

    auto load_stage = [&](int st, int kt) {
        int k0 = kt * 32;
        #pragma unroll
        for (int i = 0; i < 2; i++) {
            int ch = tid + (i << 8);
            int r = ch >> 2, c = (ch & 3) << 3;
            cpa16(&As[st * ASTGh + r * APADh + c], Ag + (size_t)r * lda + k0 + c);
        }
        #pragma unroll
        for (int i = 0; i < 2; i++) {
            int ch = tid + (i << 8);
            int r = ch >> 4, c = (ch & 15) << 3;
            cpa16(&Bs[st * BSTGh + r * BPADh + c], Bg + (size_t)(k0 + r) * ldb + c);
        }
    };

    uint32_t aBase = (uint32_t)__cvta_generic_to_shared(As);
    uint32_t bBase = (uint32_t)__cvta_generic_to_shared(Bs);
    int aRow[4];
    #pragma unroll
    for (int mt = 0; mt < 4; mt++)
        aRow[mt] = (mBase + mt * 16 + (lane & 15)) * APADh + ((lane >> 4) << 3);
    int bRow[2];
    #pragma unroll
    for (int p = 0; p < 2; p++)
        bRow[p] = ((lane & 7) + (((lane >> 3) & 1) << 3)) * BPADh
                  + nBase + p * 16 + (((lane >> 4) & 1) << 3);

    int kTiles = K >> 5;
    load_stage(0, 0);
    cpa_commit();
    if (kTiles > 1) load_stage(1, 1);
    cpa_commit();
    if (kTiles > 2) load_stage(2, 2);
    cpa_commit();

    int st = 0;
    for (int kt = 0; kt < kTiles; kt++) {
        cpa_wait2();
        __syncthreads();
        uint32_t aS = aBase + st * (ASTGh * 2);
        uint32_t bS = bBase + st * (BSTGh * 2);

        #pragma unroll
        for (int kk = 0; kk < 32; kk += 16) {
            uint32_t af[4][4], bf[4][2];
            #pragma unroll
            for (int mt = 0; mt < 4; mt++)
                ldsm4(af[mt][0], af[mt][1], af[mt][2], af[mt][3],
                      aS + 2 * (aRow[mt] + kk));
            #pragma unroll
            for (int p = 0; p < 2; p++)
                ldsm4t(bf[2*p][0], bf[2*p][1], bf[2*p+1][0], bf[2*p+1][1],
                       bS + 2 * (bRow[p] + kk * BPADh));
            #pragma unroll
            for (int mt = 0; mt < 4; mt++)
                #pragma unroll
                for (int nt = 0; nt < 4; nt++)
                    MMA_BF16(acc[mt][nt], af[mt][0], af[mt][1], af[mt][2], af[mt][3],
                             bf[nt][0], bf[nt][1]);
        }
        __syncthreads();
        if (kt + 3 < kTiles) load_stage(st, kt + 3);
        cpa_commit();
        st = (st == NSTAGE - 1) ? 0 : st + 1;
    }

    float* Cf = (float*)Cv + coff;
    __nv_bfloat16* Cb = (__nv_bfloat16*)Cv + coff;
    #pragma unroll
    for (int mt = 0; mt < 4; mt++) {
        #pragma unroll
        for (int nt = 0; nt < 4; nt++) {
            int row0 = blockIdx.y * 128 + mBase + mt * 16 + lr;
            int col  = blockIdx.x * 128 + nBase + nt * 8 + lc * 2;
            float b0 = bias ? bias[col]     : 0.0f;
            float b1 = bias ? bias[col + 1] : 0.0f;
            #pragma unroll
            for (int hh = 0; hh < 2; hh++) {
                int row = row0 + hh * 8;
                float c0 = acc[mt][nt][hh * 2 + 0] + b0;
                float c1 = acc[mt][nt][hh * 2 + 1] + b1;
                c0 *= scale; c1 *= scale;
                if (relu) { c0 = fmaxf(c0, 0.0f); c1 = fmaxf(c1, 0.0f); }
                size_t off = (size_t)row * ldc + col;
                if (outbf) {
                    __nv_bfloat162 h2;
                    h2.x = __float2bfloat16_rn(c0);
                    h2.y = __float2bfloat16_rn(c1);
                    *(__nv_bfloat162*)(Cb + off) = h2;
                } else {
                    *(float2*)(Cf + off) = make_float2(c0, c1);
                }
            }
        }
    }
}

#define SMEM_BN ((NSTAGE*ASTGh + NSTAGE*BSTGh) * 2)

static void bgemm(const __nv_bfloat16* A, int lda, long long sA0, long long sA1,
                  const __nv_bfloat16* B, int ldb, long long sB0, long long sB1,
                  void* C, int ldc, long long sC0, long long sC1,
                  int zdiv, int M, int N, int K, int nz,
                  const float* bias, int relu, float scale, int outbf)
{
    dim3 grid(N / 128, M / 128, nz), block(256);
    bgemm_kernel<<<grid, block, SMEM_BN>>>(A, lda, sA0, sA1, B, ldb, sB0, sB1,
                                           C, ldc, sC0, sC1, zdiv, K,
                                           bias, relu, scale, outbf);
}

extern "C" void kernel_launch(void* const* d_in, const int* in_sizes, int n_in,
                              void* d_out, int out_size)
{
    const float* data    = (const float*)d_in[0];
    const int*   attn_m  = (const int*)  d_in[1];
    const int*   view_ix = (const int*)  d_in[2];
    const float* seg     = (const float*)d_in[3];
    const float* Wq = (const float*)d_in[4];
    const float* bq = (const float*)d_in[5];
    const float* Wk = (const float*)d_in[6];
    const float* bk = (const float*)d_in[7];
    const float* Wv = (const float*)d_in[8];
    const float* bv = (const float*)d_in[9];
    const float* Wo = (const float*)d_in[10];
    const float* bo = (const float*)d_in[11];
    const float* W1 = (const float*)d_in[12];
    const float* b1 = (const float*)d_in[13];
    const float* W2 = (const float*)d_in[14];
    const float* b2 = (const float*)d_in[15];
    const float* alpha1 = (const float*)d_in[16];
    const float* bias1  = (const float*)d_in[17];
    const float* alpha2 = (const float*)d_in[18];
    const float* bias2  = (const float*)d_in[19];
    const float* alphaf = (const float*)d_in[20];
    const float* biasf  = (const float*)d_in[21];
    float* out = (float*)d_out;

    static float *px = nullptr, *ppart, *pbqkv;
    static __nv_bfloat16 *px2b, *pqkv, *pob, *pfb;
    static __nv_bfloat16 *wqkv, *wo, *w1, *w2;
    if (!px) {
        cudaGetSymbolAddress((void**)&px,    g_x);
        cudaGetSymbolAddress((void**)&ppart, g_part);
        cudaGetSymbolAddress((void**)&pbqkv, g_bqkv);
        cudaGetSymbolAddress((void**)&px2b,  g_x2b);
        cudaGetSymbolAddress((void**)&pqkv,  g_qkvb);
        cudaGetSymbolAddress((void**)&pob,   g_ob);
        cudaGetSymbolAddress((void**)&pfb,   g_fb);
        cudaGetSymbolAddress((void**)&wqkv,  g_wqkv);
        cudaGetSymbolAddress((void**)&wo,    g_wo);
        cudaGetSymbolAddress((void**)&w1,    g_w1);
        cudaGetSymbolAddress((void**)&w2,    g_w2);
        cudaFuncSetAttribute(bgemm_kernel,
                             cudaFuncAttributeMaxDynamicSharedMemorySize, SMEM_BN);
        cudaFuncSetAttribute(attn_kernel,
                             cudaFuncAttributeMaxDynamicSharedMemorySize, ATT_SMEM);
    }

    {
        int t4 = Lc * Dc * NQKV / 4;
        f2b_qkv_kernel<<<(t4 + 255) / 256, 256>>>(Wq, Wk, Wv, wqkv);
        int n4 = Lc * WSZ / 4;
        f2b_multi_kernel<<<(3 * n4 + 255) / 256, 256>>>(Wo, wo, W1, w1, W2, w2, n4);
        bias_qkv_kernel<<<(Lc * NQKV + 255) / 256, 256>>>(bq, bk, bv, pbqkv);
    }

    embed_kernel<<<(BSD + 255) / 256, 256>>>(data, seg, view_ix, px);
    ln_bf16_kernel<<<Bc * Sc, 128>>>(px, px2b, alpha1, bias1);

    for (int i = 0; i < Lc; i++) {
        // fused QKV
        bgemm(px2b, Dc, 0, 0, wqkv + (long long)i * Dc * NQKV, NQKV, 0, 0,
              pqkv, NQKV, 0, 0, 1, Bc * Sc, NQKV, Dc, 1,
              pbqkv + i * NQKV, 0, 1.0f, 1);

        // fused attention (scores + softmax + PV)
        {
            dim3 grid(2, Bc * Hc), block(512);
            attn_kernel<<<grid, block, ATT_SMEM>>>(pqkv, attn_m, pob);
        }

        // Wo: split-K=4
        bgemm(pob, HDc, 0, DKc * 2,
              wo + (long long)i * WSZ, Dc, 0, (long long)512 * Dc,
              ppart, Dc, 0, (long long)BSD,
              4, Bc * Sc, Dc, HDc / 4, 4,
              nullptr, 0, 1.0f, 0);
        reduce_ln_kernel<<<Bc * Sc, 128>>>(ppart, bo + i * Dc, px,
                                           alpha2 + i * Dc, bias2 + i * Dc,
                                           px2b, nullptr);

        // ff = relu(x2 @ W1 + b1)
        bgemm(px2b, Dc, 0, 0, w1 + (long long)i * WSZ, DFFc, 0, 0,
              pfb, DFFc, 0, 0, 1, Bc * Sc, DFFc, Dc, 1,
              b1 + i * DFFc, 1, 1.0f, 1);

        // W2: split-K=4
        bgemm(pfb, DFFc, 0, DKc * 2,
              w2 + (long long)i * WSZ, Dc, 0, (long long)512 * Dc,
              ppart, Dc, 0, (long long)BSD,
              4, Bc * Sc, Dc, DFFc / 4, 4,
              nullptr, 0, 1.0f, 0);

        if (i < Lc - 1)
            reduce_ln_kernel<<<Bc * Sc, 128>>>(ppart, b2 + i * Dc, px,
                                               alpha1 + (i + 1) * Dc, bias1 + (i + 1) * Dc,
                                               px2b, nullptr);
        else
            reduce_ln_kernel<<<Bc * Sc, 128>>>(ppart, b2 + i * Dc, px,
                                               alphaf, biasf,
                                               nullptr, out);
    }
}